// round 13
// baseline (speedup 1.0000x reference)
#include <cuda_runtime.h>
#include <cuda_fp16.h>
#include <mma.h>

// ---------------------------------------------------------------------------
// MAHGN R13: R12 + tensor-core GEMM (wmma m16n16k16, fp16 in / fp32 acc).
// x converted fp32->fp16 on the smem-load path; epilogue computes a_s
// directly (thread owns row x 32-col half = exactly 2 heads).
// Everything else byte-identical to R12.
// ---------------------------------------------------------------------------

using namespace nvcuda;

#define NU 200000
#define NA 100000
#define NC 500
#define DD 64
#define MAXE 4400000
#define TOTROWS 1001000

__constant__ int c_nd[8]   = {NA, NU, NU, NU, NC, NA, NC, NU};
__constant__ int c_boff[8] = {0, 98, 294, 490, 686, 687, 785, 786};
#define NBLK_SCAN 982
// sX 128x72 half (18432B) + sW 64x64 half (8192B) + sO 128x68 float (34816B)
#define GEMM_SMEM (18432 + 8192 + 34816)

// features / accumulators
__device__ float  g_xu[NU*DD], g_xa[NA*DD], g_xc[NC*DD];
__device__ float  g_oc[NC*DD];
__device__ __half g_hsA[(size_t)TOTROWS*DD];              // fp16 per-type hs slices
__device__ float  g_asA[TOTROWS*4];
__device__ float  g_adA[1000000*4];
__device__ float  g_ad[NU*4];
__device__ float  g_accu[NU*DD], g_acci[NA*DD];
__device__ float  g_tmpc[NC*DD], g_denc[NC*4];

// CSR scratch
__device__ int g_cnt8[8][NU];
__device__ int g_cur8[8][NU];
__device__ int g_indptr[8][NU+1];
__device__ int g_bsum[1024];
__device__ int g_rows[MAXE];

__device__ __forceinline__ float* xp(int s){ return s==0 ? g_xu : (s==1 ? g_xa : g_xc); }

// ---------------------------------------------------------------------------
__global__ void k_init(const float* __restrict__ xu, const float* __restrict__ xa,
                       const float* __restrict__ xc){
    int i = blockIdx.x * blockDim.x + threadIdx.x;
    if (i < 8*NU) ((int*)g_cnt8)[i] = 0;
    if (i < NU*DD){
        float v = xu[i]; g_xu[i] = v; g_accu[i] = v;
    } else if (i < (NU+NA)*DD){
        int j = i - NU*DD;
        float v = xa[j]; g_xa[j] = v; g_acci[j] = v;
    } else if (i < (NU+NA+NC)*DD){
        int j = i - (NU+NA)*DD;
        g_xc[j] = xc[j]; g_oc[j] = 0.f;
    }
}

// ---------------------------------------------------------------------------
// CSR build (proven)
// ---------------------------------------------------------------------------
#define PICK_TYPE \
    const int* ei; int base, next, t; \
    if      (i < c1){ ei = e0; base = 0;  next = c1; t = 0; } \
    else if (i < c2){ ei = e1; base = c1; next = c2; t = 1; } \
    else if (i < c3){ ei = e2; base = c2; next = c3; t = 2; } \
    else if (i < c4){ ei = e3; base = c3; next = c4; t = 3; } \
    else if (i < c5){ ei = e4; base = c4; next = c5; t = 4; } \
    else if (i < c6){ ei = e5; base = c5; next = c6; t = 5; } \
    else if (i < c7){ ei = e6; base = c6; next = c7; t = 6; } \
    else            { ei = e7; base = c7; next = cT; t = 7; } \
    int E = next - base, local = i - base;

__global__ void k_count_all(const int* e0,const int* e1,const int* e2,const int* e3,
                            const int* e4,const int* e5,const int* e6,const int* e7,
                            int c1,int c2,int c3,int c4,int c5,int c6,int c7,int cT){
    int i = blockIdx.x * blockDim.x + threadIdx.x;
    if (i >= cT) return;
    PICK_TYPE
    atomicAdd(&g_cnt8[t][ei[E + local]], 1);
}

__global__ void k_scan1(){
    __shared__ int wsum[32];
    int b = blockIdx.x, tid = threadIdx.x, lane = tid & 31, wid = tid >> 5;
    int t;
    if      (b < 98)  t = 0;
    else if (b < 294) t = 1;
    else if (b < 490) t = 2;
    else if (b < 686) t = 3;
    else if (b < 687) t = 4;
    else if (b < 785) t = 5;
    else if (b < 786) t = 6;
    else              t = 7;
    int i = (b - c_boff[t]) * 1024 + tid;
    int nd = c_nd[t];
    int v = (i < nd) ? g_cnt8[t][i] : 0;
    int x = v;
#pragma unroll
    for (int o = 1; o < 32; o <<= 1){
        int y = __shfl_up_sync(0xffffffffu, x, o);
        if (lane >= o) x += y;
    }
    if (lane == 31) wsum[wid] = x;
    __syncthreads();
    if (wid == 0){
        int s = wsum[lane];
#pragma unroll
        for (int o = 1; o < 32; o <<= 1){
            int y = __shfl_up_sync(0xffffffffu, s, o);
            if (lane >= o) s += y;
        }
        wsum[lane] = s;
    }
    __syncthreads();
    int excl = (x - v) + (wid ? wsum[wid - 1] : 0);
    if (i < nd) g_indptr[t][i] = excl;
    if (tid == 0) g_bsum[b] = wsum[31];
}

__global__ void k_scan2(){
    int w = threadIdx.x >> 5, lane = threadIdx.x & 31;
    if (w >= 8) return;
    const int nbs[8] = {98, 196, 196, 196, 1, 98, 1, 196};
    int off = c_boff[w], nb = nbs[w];
    int carry = 0;
    for (int base = 0; base < nb; base += 32){
        int i = base + lane;
        int v = (i < nb) ? g_bsum[off + i] : 0;
        int x = v;
#pragma unroll
        for (int o = 1; o < 32; o <<= 1){
            int y = __shfl_up_sync(0xffffffffu, x, o);
            if (lane >= o) x += y;
        }
        if (i < nb) g_bsum[off + i] = x - v + carry;
        carry += __shfl_sync(0xffffffffu, x, 31);
    }
}

__global__ void k_scan3(int e0n,int e1n,int e2n,int e3n,int e4n,int e5n,int e6n,int e7n){
    int i = blockIdx.x * blockDim.x + threadIdx.x;
    if (i >= 8*(NU+1)) return;
    int t = i / (NU+1), j = i - t*(NU+1);
    int nd = c_nd[t];
    if (j < nd){
        int v = g_indptr[t][j] + g_bsum[c_boff[t] + (j >> 10)];
        g_indptr[t][j] = v;
        g_cur8[t][j] = v;
    } else if (j == nd){
        const int ens[8] = {e0n,e1n,e2n,e3n,e4n,e5n,e6n,e7n};
        g_indptr[t][nd] = ens[t];
    }
}

__global__ void k_fill_all(const int* e0,const int* e1,const int* e2,const int* e3,
                           const int* e4,const int* e5,const int* e6,const int* e7,
                           int c1,int c2,int c3,int c4,int c5,int c6,int c7,int cT){
    int i = blockIdx.x * blockDim.x + threadIdx.x;
    if (i >= cT) return;
    PICK_TYPE
    int row = ei[local];
    int col = ei[E + local];
    int pos = atomicAdd(&g_cur8[t][col], 1);
    g_rows[base + pos] = row;
}

// ---------------------------------------------------------------------------
// GEMM v3: wmma m16n16k16, fp16 inputs / fp32 accum. 256 thr, 128 rows/block.
// Warp w computes rows w*16..+15 over all 64 cols (4 acc frags, 4 k-steps).
// Epilogue: frags -> smem fp32; thread owns (row, 32-col half) -> fp16 hs +
// both a_s head partials (no reduction needed).
// ---------------------------------------------------------------------------
__global__ void k_gemm_hs(int src_sel, int hsoff, const float* __restrict__ W,
                          const float* __restrict__ att, int N){
    extern __shared__ char dsmc[];
    __half* sX = (__half*)dsmc;                           // [128][72]
    __half* sW = (__half*)(dsmc + 128*72*2);              // [64][64]
    float*  sO = (float*) (dsmc + 128*72*2 + 64*64*2);    // [128][68]
    const float* x = xp(src_sel);
    __half* hs = g_hsA + (size_t)hsoff * 64;
    float*  as = g_asA + (size_t)hsoff * 4;
    int tid = threadIdx.x;
    int wid = tid >> 5;

    // W fp32 -> fp16 smem (row-major K x N, ld=64)
    for (int i = tid; i < 4096; i += 256) sW[i] = __float2half_rn(W[i]);

    int row0 = blockIdx.x * 128;
    // x fp32 -> fp16 smem (128 rows x 64 cols, ld=72)
    for (int i = tid; i < 2048; i += 256){
        int r = i >> 4, c4 = i & 15;
        int gr = row0 + r;
        float4 v = (gr < N) ? ((const float4*)x)[(size_t)gr*16 + c4]
                            : make_float4(0.f, 0.f, 0.f, 0.f);
        __half2* dst = (__half2*)&sX[r*72 + c4*4];
        dst[0] = __floats2half2_rn(v.x, v.y);
        dst[1] = __floats2half2_rn(v.z, v.w);
    }
    __syncthreads();

    wmma::fragment<wmma::accumulator, 16, 16, 16, float> acc[4];
#pragma unroll
    for (int n = 0; n < 4; n++) wmma::fill_fragment(acc[n], 0.f);
#pragma unroll
    for (int k = 0; k < 4; k++){
        wmma::fragment<wmma::matrix_a, 16, 16, 16, __half, wmma::row_major> fa;
        wmma::load_matrix_sync(fa, &sX[(wid*16)*72 + k*16], 72);
#pragma unroll
        for (int n = 0; n < 4; n++){
            wmma::fragment<wmma::matrix_b, 16, 16, 16, __half, wmma::row_major> fb;
            wmma::load_matrix_sync(fb, &sW[(k*16)*64 + n*16], 64);
            wmma::mma_sync(acc[n], fa, fb, acc[n]);
        }
    }
#pragma unroll
    for (int n = 0; n < 4; n++)
        wmma::store_matrix_sync(&sO[(wid*16)*68 + n*16], acc[n], 68, wmma::mem_row_major);
    __syncthreads();

    // epilogue: tid -> (row = tid>>1, half hf = tid&1); cols hf*32..+31
    int r = tid >> 1, hf = tid & 1;
    int gr = row0 + r;
    if (gr < N){
        const float* src = &sO[r*68 + hf*32];
        float p0 = 0.f, p1 = 0.f;
        __half hbuf[32];
#pragma unroll
        for (int c = 0; c < 32; c++){
            float v = src[c];
            hbuf[c] = __float2half_rn(v);
            float a = __ldg(&att[hf*32 + c]);
            if (c < 16) p0 += v * a; else p1 += v * a;
        }
        uint4* dst = (uint4*)&hs[(size_t)gr*64 + hf*32];
        const uint4* sb = (const uint4*)hbuf;
        dst[0] = sb[0]; dst[1] = sb[1];
        dst[2] = sb[2]; dst[3] = sb[3];
        as[gr*4 + hf*2]     = p0;
        as[gr*4 + hf*2 + 1] = p1;
    }
}

// ---------------------------------------------------------------------------
// a_d for up to 4 incoming types (R10-proven)
// ---------------------------------------------------------------------------
__global__ void k_ad_multi(int dst_sel, int N, int nT,
                           int4 woff, int4 aoff, int4 doff,
                           const float* __restrict__ Wdst,
                           const float* __restrict__ attd){
    __shared__ float sWd[4][64][4];
    __shared__ float sX[64][65];
    const float* x = xp(dst_sel);
    int tid = threadIdx.x;
    int wo[4] = {woff.x, woff.y, woff.z, woff.w};
    int ao[4] = {aoff.x, aoff.y, aoff.z, aoff.w};
    int dofs[4] = {doff.x, doff.y, doff.z, doff.w};

    {
        int k = tid >> 2, h = tid & 3;
#pragma unroll
        for (int q = 0; q < 4; q++){
            if (q < nT){
                const float* Wd = Wdst + wo[q];
                const float* at = attd + ao[q];
                float s = 0.f;
#pragma unroll
                for (int c = 0; c < 16; c++) s += Wd[k*64 + h*16 + c] * at[h*16 + c];
                sWd[q][k][h] = s;
            }
        }
    }
    int row0 = blockIdx.x * 64;
    for (int i = tid; i < 4096; i += 256){
        int r = i >> 6, c = i & 63;
        int gr = row0 + r;
        sX[r][c] = (gr < N) ? x[gr*64 + c] : 0.f;
    }
    __syncthreads();

    int r = tid >> 2, h = tid & 3;
    int gr = row0 + r;
    if (gr < N){
#pragma unroll
        for (int q = 0; q < 4; q++){
            if (q < nT){
                float s = 0.f;
#pragma unroll
                for (int k = 0; k < 64; k++) s += sX[r][k] * sWd[q][k][h];
                g_adA[(size_t)(dofs[q] + gr)*4 + h] = s;
            }
        }
    }
}

// ---------------------------------------------------------------------------
// a_d for the category path (proven; zeroes partial buffers)
// ---------------------------------------------------------------------------
__global__ void k_ad(int dst_sel, const float* __restrict__ Wd,
                     const float* __restrict__ attd, int N, int zc){
    __shared__ float sWd[64][4];
    __shared__ float sX[64][65];
    const float* x = xp(dst_sel);
    int tid = threadIdx.x;

    {
        int k = tid >> 2, h = tid & 3;
        float s = 0.f;
#pragma unroll
        for (int c = 0; c < 16; c++) s += Wd[k*64 + h*16 + c] * attd[h*16 + c];
        sWd[k][h] = s;
    }
    int row0 = blockIdx.x * 64;
    for (int i = tid; i < 4096; i += 256){
        int r = i >> 6, c = i & 63;
        int gr = row0 + r;
        sX[r][c] = (gr < N) ? x[gr*64 + c] : 0.f;
    }
    __syncthreads();

    int r = tid >> 2, h = tid & 3;
    int gr = row0 + r;
    if (gr < N){
        float s = 0.f;
#pragma unroll
        for (int k = 0; k < 64; k++) s += sX[r][k] * sWd[k][h];
        g_ad[gr*4 + h] = s;
        if (zc){
            g_denc[gr*4 + h] = 0.f;
            float4 z = make_float4(0.f,0.f,0.f,0.f);
            float4* tz = (float4*)&g_tmpc[gr*64 + h*16];
            tz[0] = z; tz[1] = z; tz[2] = z; tz[3] = z;
        }
    }
}

// ---------------------------------------------------------------------------
// edge segment body, half2 layout (R12-proven)
// ---------------------------------------------------------------------------
__device__ __forceinline__ void do_edges(const int* __restrict__ rows, int beg, int end,
                                         const __half* __restrict__ hs,
                                         const float* __restrict__ as,
                                         int lane, int h, float adh,
                                         float& a0, float& a1, float& d){
    const __half2* hs2 = (const __half2*)hs;
    int e = beg;
    for (; e + 4 <= end; e += 4){
        int r0 = __ldg(rows + e + 0), r1 = __ldg(rows + e + 1);
        int r2 = __ldg(rows + e + 2), r3 = __ldg(rows + e + 3);
        float s0 = __ldg(&as[r0*4 + h]);
        float s1 = __ldg(&as[r1*4 + h]);
        float s2 = __ldg(&as[r2*4 + h]);
        float s3 = __ldg(&as[r3*4 + h]);
        __half2 u0 = __ldg(&hs2[(size_t)r0*32 + lane]);
        __half2 u1 = __ldg(&hs2[(size_t)r1*32 + lane]);
        __half2 u2 = __ldg(&hs2[(size_t)r2*32 + lane]);
        __half2 u3 = __ldg(&hs2[(size_t)r3*32 + lane]);

        float e0 = s0 + adh, e1 = s1 + adh, e2 = s2 + adh, e3 = s3 + adh;
        e0 = e0 > 0.f ? e0 : 0.2f*e0;
        e1 = e1 > 0.f ? e1 : 0.2f*e1;
        e2 = e2 > 0.f ? e2 : 0.2f*e2;
        e3 = e3 > 0.f ? e3 : 0.2f*e3;
        float x0 = __expf(e0), x1 = __expf(e1), x2 = __expf(e2), x3 = __expf(e3);

        float2 f0 = __half22float2(u0);
        float2 f1 = __half22float2(u1);
        float2 f2 = __half22float2(u2);
        float2 f3 = __half22float2(u3);
        a0 += x0*f0.x + x1*f1.x + x2*f2.x + x3*f3.x;
        a1 += x0*f0.y + x1*f1.y + x2*f2.y + x3*f3.y;
        d  += x0 + x1 + x2 + x3;
    }
    for (; e < end; e++){
        int row = __ldg(rows + e);
        float ev = __ldg(&as[row*4 + h]) + adh;
        ev = ev > 0.f ? ev : 0.2f*ev;
        float ex = __expf(ev);
        float2 f = __half22float2(__ldg(&hs2[(size_t)row*32 + lane]));
        a0 += ex*f.x; a1 += ex*f.y; d += ex;
    }
}

__device__ __forceinline__ void aggr_one(int t, int gw, int eoff, int hsoff, int adoff,
                                         int lane, int h, float& o0, float& o1){
    int beg = g_indptr[t][gw], end = g_indptr[t][gw + 1];
    if (beg >= end) return;
    float adh = g_adA[(size_t)(adoff + gw)*4 + h];
    float a0 = 0.f, a1 = 0.f, d = 0.f;
    do_edges(g_rows + eoff, beg, end,
             g_hsA + (size_t)hsoff*64, g_asA + (size_t)hsoff*4,
             lane, h, adh, a0, a1, d);
    float inv = 1.f / (d + 1e-16f);
    o0 += a0 * inv;
    o1 += a1 * inv;
}

// ---------------------------------------------------------------------------
__global__ void k_aggr_user(int e1, int e2, int e3, int e7,
                            const float* __restrict__ bias, int l){
    int gw = (blockIdx.x * blockDim.x + threadIdx.x) >> 5;
    if (gw >= NU) return;
    int lane = threadIdx.x & 31, h = lane >> 3;
    int c0 = 2*lane, c1 = 2*lane + 1;
    const float* bl = bias + l*512;
    float o0 = bl[64+c0] + bl[128+c0] + bl[192+c0] + bl[448+c0];
    float o1 = bl[64+c1] + bl[128+c1] + bl[192+c1] + bl[448+c1];

    aggr_one(1, gw, e1, 200000,  100000, lane, h, o0, o1);
    aggr_one(2, gw, e2, 300000,  300000, lane, h, o0, o1);
    aggr_one(3, gw, e3, 500000,  500000, lane, h, o0, o1);
    aggr_one(7, gw, e7, 1000500, 800000, lane, h, o0, o1);

    float v0 = o0 > 0.f ? o0 : 0.01f*o0;
    float v1 = o1 > 0.f ? o1 : 0.01f*o1;
    *(float2*)&g_xu[(size_t)gw*64 + c0] = make_float2(v0, v1);
    float2 au = *(float2*)&g_accu[(size_t)gw*64 + c0];
    au.x += v0; au.y += v1;
    *(float2*)&g_accu[(size_t)gw*64 + c0] = au;
}

__global__ void k_aggr_article(int e0, int e5, const float* __restrict__ bias, int l){
    int gw = (blockIdx.x * blockDim.x + threadIdx.x) >> 5;
    if (gw >= NA) return;
    int lane = threadIdx.x & 31, h = lane >> 3;
    int c0 = 2*lane, c1 = 2*lane + 1;
    const float* bl = bias + l*512;
    float o0 = bl[0+c0] + bl[320+c0];
    float o1 = bl[0+c1] + bl[320+c1];

    aggr_one(0, gw, e0, 0,      0,      lane, h, o0, o1);
    aggr_one(5, gw, e5, 800000, 700000, lane, h, o0, o1);

    float v0 = o0 > 0.f ? o0 : 0.01f*o0;
    float v1 = o1 > 0.f ? o1 : 0.01f*o1;
    *(float2*)&g_xa[(size_t)gw*64 + c0] = make_float2(v0, v1);
    float2 au = *(float2*)&g_acci[(size_t)gw*64 + c0];
    au.x += v0; au.y += v1;
    *(float2*)&g_acci[(size_t)gw*64 + c0] = au;
}

// ---------------------------------------------------------------------------
#define CCHUNK 64
__global__ void k_aggr_cat(int t, int eoff, int E, int hsoff){
    int w = (blockIdx.x * blockDim.x + threadIdx.x) >> 5;
    int lane = threadIdx.x & 31;
    int es = w * CCHUNK;
    if (es >= E) return;
    int ee = min(es + CCHUNK, E);
    const int* __restrict__ ip = g_indptr[t];

    int lo = 0, hi = NC;
    while (lo < hi){
        int mid = (lo + hi + 1) >> 1;
        if (ip[mid] <= es) lo = mid; else hi = mid - 1;
    }
    int n = lo;
    int h = lane >> 3;
    int c0 = 2*lane;
    const int* rows = g_rows + eoff;
    const __half* hs = g_hsA + (size_t)hsoff*64;
    const float* as = g_asA + (size_t)hsoff*4;

    while (es < ee){
        int segend = min(ip[n + 1], ee);
        float adh = g_ad[n*4 + h];
        float a0 = 0.f, a1 = 0.f, d = 0.f;
        do_edges(rows, es, segend, hs, as, lane, h, adh, a0, a1, d);
        atomicAdd(&g_tmpc[n*64 + c0],     a0);
        atomicAdd(&g_tmpc[n*64 + c0 + 1], a1);
        if ((lane & 7) == 0)
            atomicAdd(&g_denc[n*4 + h], d);
        es = segend;
        n++;
    }
}

__global__ void k_norm_cat(){
    int i = blockIdx.x * blockDim.x + threadIdx.x;
    if (i >= NC*DD) return;
    int n = i >> 6, c = i & 63, h = c >> 4;
    g_oc[i] += g_tmpc[i] / (g_denc[n*4 + h] + 1e-16f);
}

__global__ void k_cat_act(const float* __restrict__ bias, int l){
    int i = blockIdx.x * blockDim.x + threadIdx.x;
    if (i >= NC*DD) return;
    int c = i & 63;
    const float* bl = bias + l*512;
    float v = g_oc[i] + bl[256 + c] + bl[384 + c];
    g_xc[i] = v > 0.f ? v : 0.01f*v;
    g_oc[i] = 0.f;
}

// ---------------------------------------------------------------------------
__global__ void k_final(float* __restrict__ out){
    int i = blockIdx.x * blockDim.x + threadIdx.x;
    const int nu = NU * DD;
    const int tot = nu + NA * DD;
    if (i >= tot) return;
    const float s = 1.f / 3.f;
    out[i] = (i < nu) ? g_accu[i] * s : g_acci[i - nu] * s;
}

// ---------------------------------------------------------------------------
static inline int cdiv(long long a, int b){ return (int)((a + b - 1) / b); }

extern "C" void kernel_launch(void* const* d_in, const int* in_sizes, int n_in,
                              void* d_out, int out_size){
    const float* x_user    = (const float*)d_in[0];
    const float* x_article = (const float*)d_in[1];
    const float* x_cat     = (const float*)d_in[2];
    const float* Wsrc      = (const float*)d_in[3];
    const float* Wdst      = (const float*)d_in[4];
    const float* att_src   = (const float*)d_in[5];
    const float* att_dst   = (const float*)d_in[6];
    const float* bias      = (const float*)d_in[7];
    float* out = (float*)d_out;

    static const int SRC[8]   = {0, 1, 0, 0, 1, 2, 0, 2};
    static const int NN[3]    = {NU, NA, NC};
    static const int HSOFF[8] = {0, 200000, 300000, 500000, 700000, 800000, 800500, 1000500};

    cudaFuncSetAttribute(k_gemm_hs, cudaFuncAttributeMaxDynamicSharedMemorySize, GEMM_SMEM);

    int EN[8], CUM[9]; CUM[0] = 0;
    for (int t = 0; t < 8; t++){ EN[t] = in_sizes[8 + t] / 2; CUM[t+1] = CUM[t] + EN[t]; }
    const int* EP[8];
    for (int t = 0; t < 8; t++) EP[t] = (const int*)d_in[8 + t];

    const int TOTN = (NU + NA + NC) * DD;

    // #1 init, #2 count, #3 scan1
    k_init     <<<cdiv(TOTN, 256), 256>>>(x_user, x_article, x_cat);
    k_count_all<<<cdiv(CUM[8], 256), 256>>>(EP[0],EP[1],EP[2],EP[3],EP[4],EP[5],EP[6],EP[7],
                                            CUM[1],CUM[2],CUM[3],CUM[4],CUM[5],CUM[6],CUM[7],CUM[8]);
    k_scan1    <<<NBLK_SCAN, 1024>>>();
    // #4 PROFILED: layer-0 t0 GEMM (wmma v3)
    k_gemm_hs  <<<cdiv(NU, 128), 256, GEMM_SMEM>>>(0, 0, Wsrc, att_src, NU);
    // #5-#7 finish CSR
    k_scan2    <<<1, 256>>>();
    k_scan3    <<<cdiv(8*(NU+1), 256), 256>>>(EN[0],EN[1],EN[2],EN[3],EN[4],EN[5],EN[6],EN[7]);
    k_fill_all <<<cdiv(CUM[8], 256), 256>>>(EP[0],EP[1],EP[2],EP[3],EP[4],EP[5],EP[6],EP[7],
                                            CUM[1],CUM[2],CUM[3],CUM[4],CUM[5],CUM[6],CUM[7],CUM[8]);

    for (int l = 0; l < 2; l++){
        for (int t = 0; t < 8; t++){
            if (l == 0 && t == 0) continue;
            const float* W  = Wsrc    + (size_t)(l*8 + t) * 4096;
            const float* as = att_src + (size_t)(l*8 + t) * 64;
            k_gemm_hs<<<cdiv(NN[SRC[t]], 128), 256, GEMM_SMEM>>>(SRC[t], HSOFF[t], W, as, NN[SRC[t]]);
        }
        {
            int b = l*8;
            int4 wu = make_int4((b+1)*4096, (b+2)*4096, (b+3)*4096, (b+7)*4096);
            int4 au = make_int4((b+1)*64,   (b+2)*64,   (b+3)*64,   (b+7)*64);
            int4 du = make_int4(100000, 300000, 500000, 800000);
            k_ad_multi<<<cdiv(NU, 64), 256>>>(0, NU, 4, wu, au, du, Wdst, att_dst);
            int4 wa = make_int4((b+0)*4096, (b+5)*4096, 0, 0);
            int4 aa = make_int4((b+0)*64,   (b+5)*64,   0, 0);
            int4 da = make_int4(0, 700000, 0, 0);
            k_ad_multi<<<cdiv(NA, 64), 256>>>(1, NA, 2, wa, aa, da, Wdst, att_dst);
        }
        k_aggr_user   <<<cdiv(NU, 8), 256>>>(CUM[1], CUM[2], CUM[3], CUM[7], bias, l);
        k_aggr_article<<<cdiv(NA, 8), 256>>>(CUM[0], CUM[5], bias, l);
        {
            const float* Wd4 = Wdst + (size_t)(l*8 + 4) * 4096;
            const float* ad4 = att_dst + (size_t)(l*8 + 4) * 64;
            k_ad<<<cdiv(NC, 64), 256>>>(2, Wd4, ad4, NC, 1);
            k_aggr_cat<<<cdiv(cdiv(EN[4], CCHUNK), 8), 256>>>(4, CUM[4], EN[4], HSOFF[4]);
            k_norm_cat<<<cdiv(NC*DD, 256), 256>>>();
            const float* Wd6 = Wdst + (size_t)(l*8 + 6) * 4096;
            const float* ad6 = att_dst + (size_t)(l*8 + 6) * 64;
            k_ad<<<cdiv(NC, 64), 256>>>(2, Wd6, ad6, NC, 1);
            k_aggr_cat<<<cdiv(cdiv(EN[6], CCHUNK), 8), 256>>>(6, CUM[6], EN[6], HSOFF[6]);
            k_norm_cat<<<cdiv(NC*DD, 256), 256>>>();
        }
        k_cat_act<<<cdiv(NC*DD, 256), 256>>>(bias, l);
    }

    k_final<<<cdiv((long long)(NU + NA) * DD, 256), 256>>>(out);
}

// round 14
// speedup vs baseline: 1.2319x; 1.2319x over previous
#include <cuda_runtime.h>
#include <cuda_fp16.h>

// ---------------------------------------------------------------------------
// MAHGN R14: R12 math (scalar register-tiled GEMM, fp16 hs, half2 aggr) with
// dispatch-level launch merging: 1 GEMM launch/layer, merged ad, merged
// user+article aggregation, merged cat path. 47 -> 20 launches.
// ---------------------------------------------------------------------------

#define NU 200000
#define NA 100000
#define NC 500
#define DD 64
#define MAXE 4400000
#define TOTROWS 1001000

__constant__ int c_nd[8]   = {NA, NU, NU, NU, NC, NA, NC, NU};
__constant__ int c_boff[8] = {0, 98, 294, 490, 686, 687, 785, 786};
#define NBLK_SCAN 982
#define GEMM_SMEM (16384 + 33280)

// batched-GEMM block ranges (128 rows/block):
// ns {NU,NA,NU,NU,NA,NC,NU,NC} -> blocks {1563,782,1563,1563,782,4,1563,4}
__constant__ int gb_cum[9]   = {0, 1563, 2345, 3908, 5471, 6253, 6257, 7820, 7824};
__constant__ int gb_src[8]   = {0, 1, 0, 0, 1, 2, 0, 2};
__constant__ int gb_n[8]     = {NU, NA, NU, NU, NA, NC, NU, NC};
__constant__ int gb_hsoff[8] = {0, 200000, 300000, 500000, 700000, 800000, 800500, 1000500};
#define GEMM_BLOCKS 7824

// features / accumulators
__device__ float  g_xu[NU*DD], g_xa[NA*DD], g_xc[NC*DD];
__device__ __half g_hsA[(size_t)TOTROWS*DD];
__device__ float  g_asA[TOTROWS*4];
__device__ float  g_adA[1000000*4];
__device__ float  g_adc4[NC*4], g_adc6[NC*4];
__device__ float  g_accu[NU*DD], g_acci[NA*DD];
__device__ float  g_tmpc0[NC*DD], g_tmpc1[NC*DD], g_denc0[NC*4], g_denc1[NC*4];

// CSR scratch
__device__ int g_cnt8[8][NU];
__device__ int g_cur8[8][NU];
__device__ int g_indptr[8][NU+1];
__device__ int g_bsum[1024];
__device__ int g_rows[MAXE];

__device__ __forceinline__ float* xp(int s){ return s==0 ? g_xu : (s==1 ? g_xa : g_xc); }

// ---------------------------------------------------------------------------
__global__ void k_init(const float* __restrict__ xu, const float* __restrict__ xa,
                       const float* __restrict__ xc){
    int i = blockIdx.x * blockDim.x + threadIdx.x;
    if (i < 8*NU) ((int*)g_cnt8)[i] = 0;
    if (i < NU*DD){
        float v = xu[i]; g_xu[i] = v; g_accu[i] = v;
    } else if (i < (NU+NA)*DD){
        int j = i - NU*DD;
        float v = xa[j]; g_xa[j] = v; g_acci[j] = v;
    } else if (i < (NU+NA+NC)*DD){
        int j = i - (NU+NA)*DD;
        g_xc[j] = xc[j];
    }
}

// ---------------------------------------------------------------------------
// CSR build (proven)
// ---------------------------------------------------------------------------
#define PICK_TYPE \
    const int* ei; int base, next, t; \
    if      (i < c1){ ei = e0; base = 0;  next = c1; t = 0; } \
    else if (i < c2){ ei = e1; base = c1; next = c2; t = 1; } \
    else if (i < c3){ ei = e2; base = c2; next = c3; t = 2; } \
    else if (i < c4){ ei = e3; base = c3; next = c4; t = 3; } \
    else if (i < c5){ ei = e4; base = c4; next = c5; t = 4; } \
    else if (i < c6){ ei = e5; base = c5; next = c6; t = 5; } \
    else if (i < c7){ ei = e6; base = c6; next = c7; t = 6; } \
    else            { ei = e7; base = c7; next = cT; t = 7; } \
    int E = next - base, local = i - base;

__global__ void k_count_all(const int* e0,const int* e1,const int* e2,const int* e3,
                            const int* e4,const int* e5,const int* e6,const int* e7,
                            int c1,int c2,int c3,int c4,int c5,int c6,int c7,int cT){
    int i = blockIdx.x * blockDim.x + threadIdx.x;
    if (i >= cT) return;
    PICK_TYPE
    atomicAdd(&g_cnt8[t][ei[E + local]], 1);
}

__global__ void k_scan1(){
    __shared__ int wsum[32];
    int b = blockIdx.x, tid = threadIdx.x, lane = tid & 31, wid = tid >> 5;
    int t;
    if      (b < 98)  t = 0;
    else if (b < 294) t = 1;
    else if (b < 490) t = 2;
    else if (b < 686) t = 3;
    else if (b < 687) t = 4;
    else if (b < 785) t = 5;
    else if (b < 786) t = 6;
    else              t = 7;
    int i = (b - c_boff[t]) * 1024 + tid;
    int nd = c_nd[t];
    int v = (i < nd) ? g_cnt8[t][i] : 0;
    int x = v;
#pragma unroll
    for (int o = 1; o < 32; o <<= 1){
        int y = __shfl_up_sync(0xffffffffu, x, o);
        if (lane >= o) x += y;
    }
    if (lane == 31) wsum[wid] = x;
    __syncthreads();
    if (wid == 0){
        int s = wsum[lane];
#pragma unroll
        for (int o = 1; o < 32; o <<= 1){
            int y = __shfl_up_sync(0xffffffffu, s, o);
            if (lane >= o) s += y;
        }
        wsum[lane] = s;
    }
    __syncthreads();
    int excl = (x - v) + (wid ? wsum[wid - 1] : 0);
    if (i < nd) g_indptr[t][i] = excl;
    if (tid == 0) g_bsum[b] = wsum[31];
}

__global__ void k_scan2(){
    int w = threadIdx.x >> 5, lane = threadIdx.x & 31;
    if (w >= 8) return;
    const int nbs[8] = {98, 196, 196, 196, 1, 98, 1, 196};
    int off = c_boff[w], nb = nbs[w];
    int carry = 0;
    for (int base = 0; base < nb; base += 32){
        int i = base + lane;
        int v = (i < nb) ? g_bsum[off + i] : 0;
        int x = v;
#pragma unroll
        for (int o = 1; o < 32; o <<= 1){
            int y = __shfl_up_sync(0xffffffffu, x, o);
            if (lane >= o) x += y;
        }
        if (i < nb) g_bsum[off + i] = x - v + carry;
        carry += __shfl_sync(0xffffffffu, x, 31);
    }
}

__global__ void k_scan3(int e0n,int e1n,int e2n,int e3n,int e4n,int e5n,int e6n,int e7n){
    int i = blockIdx.x * blockDim.x + threadIdx.x;
    if (i >= 8*(NU+1)) return;
    int t = i / (NU+1), j = i - t*(NU+1);
    int nd = c_nd[t];
    if (j < nd){
        int v = g_indptr[t][j] + g_bsum[c_boff[t] + (j >> 10)];
        g_indptr[t][j] = v;
        g_cur8[t][j] = v;
    } else if (j == nd){
        const int ens[8] = {e0n,e1n,e2n,e3n,e4n,e5n,e6n,e7n};
        g_indptr[t][nd] = ens[t];
    }
}

__global__ void k_fill_all(const int* e0,const int* e1,const int* e2,const int* e3,
                           const int* e4,const int* e5,const int* e6,const int* e7,
                           int c1,int c2,int c3,int c4,int c5,int c6,int c7,int cT){
    int i = blockIdx.x * blockDim.x + threadIdx.x;
    if (i >= cT) return;
    PICK_TYPE
    int row = ei[local];
    int col = ei[E + local];
    int pos = atomicAdd(&g_cur8[t][col], 1);
    g_rows[base + pos] = row;
}

// ---------------------------------------------------------------------------
// Batched GEMM: all 8 types in one launch (R12-proven inner math).
// ---------------------------------------------------------------------------
__global__ void k_gemm_all(const float* __restrict__ Wsrc,
                           const float* __restrict__ att_src, int l){
    extern __shared__ float dsm[];
    float* sW = dsm;
    float* sX = dsm + 4096;
    int b = blockIdx.x;
    int t = 0;
#pragma unroll
    for (int q = 1; q < 8; q++) if (b >= gb_cum[q]) t = q;
    int src_sel = gb_src[t];
    int N = gb_n[t];
    const float* x = xp(src_sel);
    const float* W   = Wsrc    + (size_t)(l*8 + t) * 4096;
    const float* att = att_src + (size_t)(l*8 + t) * 64;
    __half* hs = g_hsA + (size_t)gb_hsoff[t] * 64;
    float*  as = g_asA + (size_t)gb_hsoff[t] * 4;
    int tid = threadIdx.x;

    for (int i = tid; i < 1024; i += 256)
        ((float4*)sW)[i] = ((const float4*)W)[i];

    int row0 = (b - gb_cum[t]) * 128;
    for (int i = tid; i < 2048; i += 256){
        int r = i >> 4, c4 = i & 15;
        int gr = row0 + r;
        float4 v = (gr < N) ? ((const float4*)x)[(size_t)gr*16 + c4]
                            : make_float4(0.f, 0.f, 0.f, 0.f);
        sX[r*65 + c4*4+0] = v.x; sX[r*65 + c4*4+1] = v.y;
        sX[r*65 + c4*4+2] = v.z; sX[r*65 + c4*4+3] = v.w;
    }
    __syncthreads();

    int rp = tid >> 3, cg = tid & 7;
    int r0 = rp * 4;
    int cA = cg * 4, cB = 32 + cg * 4;
    float4 attA = __ldg((const float4*)&att[cA]);
    float4 attB = __ldg((const float4*)&att[cB]);

    float acc[4][8];
#pragma unroll
    for (int i = 0; i < 4; i++)
#pragma unroll
        for (int j = 0; j < 8; j++) acc[i][j] = 0.f;

#pragma unroll 8
    for (int k = 0; k < 64; k++){
        float4 w0 = *(const float4*)&sW[k*64 + cA];
        float4 w1 = *(const float4*)&sW[k*64 + cB];
#pragma unroll
        for (int i = 0; i < 4; i++){
            float xv = sX[(r0 + i)*65 + k];
            acc[i][0] += xv * w0.x; acc[i][1] += xv * w0.y;
            acc[i][2] += xv * w0.z; acc[i][3] += xv * w0.w;
            acc[i][4] += xv * w1.x; acc[i][5] += xv * w1.y;
            acc[i][6] += xv * w1.z; acc[i][7] += xv * w1.w;
        }
    }

#pragma unroll
    for (int i = 0; i < 4; i++){
        int gr = row0 + r0 + i;
        float pA = acc[i][0]*attA.x + acc[i][1]*attA.y + acc[i][2]*attA.z + acc[i][3]*attA.w;
        float pB = acc[i][4]*attB.x + acc[i][5]*attB.y + acc[i][6]*attB.z + acc[i][7]*attB.w;
        pA += __shfl_xor_sync(0xffffffffu, pA, 1);
        pA += __shfl_xor_sync(0xffffffffu, pA, 2);
        pB += __shfl_xor_sync(0xffffffffu, pB, 1);
        pB += __shfl_xor_sync(0xffffffffu, pB, 2);
        if (gr < N){
            union { __half2 h2[2]; uint2 u; } pk;
            pk.h2[0] = __floats2half2_rn(acc[i][0], acc[i][1]);
            pk.h2[1] = __floats2half2_rn(acc[i][2], acc[i][3]);
            *(uint2*)&hs[(size_t)gr*64 + cA] = pk.u;
            pk.h2[0] = __floats2half2_rn(acc[i][4], acc[i][5]);
            pk.h2[1] = __floats2half2_rn(acc[i][6], acc[i][7]);
            *(uint2*)&hs[(size_t)gr*64 + cB] = pk.u;
            if ((cg & 3) == 0){
                int h01 = cg >> 2;
                as[gr*4 + h01]     = pA;
                as[gr*4 + 2 + h01] = pB;
            }
        }
    }
}

// ---------------------------------------------------------------------------
// merged a_d: user dst (t1,t2,t3,t7) blocks [0,3125), article (t0,t5) after.
// inner math = R10-proven k_ad_multi.
// ---------------------------------------------------------------------------
__global__ void k_ad_all(const float* __restrict__ Wdst,
                         const float* __restrict__ attd, int l){
    __shared__ float sWd[4][64][4];
    __shared__ float sX[64][65];
    int b = blockIdx.x;
    int dst_sel, N, nT, row0;
    int tl[4], dofs[4];
    if (b < 3125){
        dst_sel = 0; N = NU; nT = 4; row0 = b * 64;
        tl[0]=1; tl[1]=2; tl[2]=3; tl[3]=7;
        dofs[0]=100000; dofs[1]=300000; dofs[2]=500000; dofs[3]=800000;
    } else {
        dst_sel = 1; N = NA; nT = 2; row0 = (b - 3125) * 64;
        tl[0]=0; tl[1]=5; tl[2]=0; tl[3]=0;
        dofs[0]=0; dofs[1]=700000; dofs[2]=0; dofs[3]=0;
    }
    const float* x = xp(dst_sel);
    int tid = threadIdx.x;

    {
        int k = tid >> 2, h = tid & 3;
#pragma unroll
        for (int q = 0; q < 4; q++){
            if (q < nT){
                const float* Wd = Wdst + (size_t)(l*8 + tl[q]) * 4096;
                const float* at = attd + (size_t)(l*8 + tl[q]) * 64;
                float s = 0.f;
#pragma unroll
                for (int c = 0; c < 16; c++) s += Wd[k*64 + h*16 + c] * at[h*16 + c];
                sWd[q][k][h] = s;
            }
        }
    }
    for (int i = tid; i < 4096; i += 256){
        int r = i >> 6, c = i & 63;
        int gr = row0 + r;
        sX[r][c] = (gr < N) ? x[gr*64 + c] : 0.f;
    }
    __syncthreads();

    int r = tid >> 2, h = tid & 3;
    int gr = row0 + r;
    if (gr < N){
#pragma unroll
        for (int q = 0; q < 4; q++){
            if (q < nT){
                float s = 0.f;
#pragma unroll
                for (int k = 0; k < 64; k++) s += sX[r][k] * sWd[q][k][h];
                g_adA[(size_t)(dofs[q] + gr)*4 + h] = s;
            }
        }
    }
}

// ---------------------------------------------------------------------------
// merged cat a_d: t4 and t6 folded vectors; also zero partial buffers.
// ---------------------------------------------------------------------------
__global__ void k_ad_cat(const float* __restrict__ Wdst,
                         const float* __restrict__ attd, int l){
    __shared__ float sWd[2][64][4];
    __shared__ float sX[64][65];
    int tid = threadIdx.x;
    const int tl[2] = {4, 6};
    {
        int k = tid >> 2, h = tid & 3;
#pragma unroll
        for (int q = 0; q < 2; q++){
            const float* Wd = Wdst + (size_t)(l*8 + tl[q]) * 4096;
            const float* at = attd + (size_t)(l*8 + tl[q]) * 64;
            float s = 0.f;
#pragma unroll
            for (int c = 0; c < 16; c++) s += Wd[k*64 + h*16 + c] * at[h*16 + c];
            sWd[q][k][h] = s;
        }
    }
    int row0 = blockIdx.x * 64;
    for (int i = tid; i < 4096; i += 256){
        int r = i >> 6, c = i & 63;
        int gr = row0 + r;
        sX[r][c] = (gr < NC) ? g_xc[gr*64 + c] : 0.f;
    }
    __syncthreads();

    int r = tid >> 2, h = tid & 3;
    int gr = row0 + r;
    if (gr < NC){
        float s4 = 0.f, s6 = 0.f;
#pragma unroll
        for (int k = 0; k < 64; k++){
            float xv = sX[r][k];
            s4 += xv * sWd[0][k][h];
            s6 += xv * sWd[1][k][h];
        }
        g_adc4[gr*4 + h] = s4;
        g_adc6[gr*4 + h] = s6;
        g_denc0[gr*4 + h] = 0.f;
        g_denc1[gr*4 + h] = 0.f;
        float4 z = make_float4(0.f,0.f,0.f,0.f);
        float4* t0 = (float4*)&g_tmpc0[gr*64 + h*16];
        float4* t1 = (float4*)&g_tmpc1[gr*64 + h*16];
        t0[0]=z; t0[1]=z; t0[2]=z; t0[3]=z;
        t1[0]=z; t1[1]=z; t1[2]=z; t1[3]=z;
    }
}

// ---------------------------------------------------------------------------
// edge segment body, half2 layout (R12-proven)
// ---------------------------------------------------------------------------
__device__ __forceinline__ void do_edges(const int* __restrict__ rows, int beg, int end,
                                         const __half* __restrict__ hs,
                                         const float* __restrict__ as,
                                         int lane, int h, float adh,
                                         float& a0, float& a1, float& d){
    const __half2* hs2 = (const __half2*)hs;
    int e = beg;
    for (; e + 4 <= end; e += 4){
        int r0 = __ldg(rows + e + 0), r1 = __ldg(rows + e + 1);
        int r2 = __ldg(rows + e + 2), r3 = __ldg(rows + e + 3);
        float s0 = __ldg(&as[r0*4 + h]);
        float s1 = __ldg(&as[r1*4 + h]);
        float s2 = __ldg(&as[r2*4 + h]);
        float s3 = __ldg(&as[r3*4 + h]);
        __half2 u0 = __ldg(&hs2[(size_t)r0*32 + lane]);
        __half2 u1 = __ldg(&hs2[(size_t)r1*32 + lane]);
        __half2 u2 = __ldg(&hs2[(size_t)r2*32 + lane]);
        __half2 u3 = __ldg(&hs2[(size_t)r3*32 + lane]);

        float e0 = s0 + adh, e1 = s1 + adh, e2 = s2 + adh, e3 = s3 + adh;
        e0 = e0 > 0.f ? e0 : 0.2f*e0;
        e1 = e1 > 0.f ? e1 : 0.2f*e1;
        e2 = e2 > 0.f ? e2 : 0.2f*e2;
        e3 = e3 > 0.f ? e3 : 0.2f*e3;
        float x0 = __expf(e0), x1 = __expf(e1), x2 = __expf(e2), x3 = __expf(e3);

        float2 f0 = __half22float2(u0);
        float2 f1 = __half22float2(u1);
        float2 f2 = __half22float2(u2);
        float2 f3 = __half22float2(u3);
        a0 += x0*f0.x + x1*f1.x + x2*f2.x + x3*f3.x;
        a1 += x0*f0.y + x1*f1.y + x2*f2.y + x3*f3.y;
        d  += x0 + x1 + x2 + x3;
    }
    for (; e < end; e++){
        int row = __ldg(rows + e);
        float ev = __ldg(&as[row*4 + h]) + adh;
        ev = ev > 0.f ? ev : 0.2f*ev;
        float ex = __expf(ev);
        float2 f = __half22float2(__ldg(&hs2[(size_t)row*32 + lane]));
        a0 += ex*f.x; a1 += ex*f.y; d += ex;
    }
}

__device__ __forceinline__ void aggr_one(int t, int gw, int eoff, int hsoff, int adoff,
                                         int lane, int h, float& o0, float& o1){
    int beg = g_indptr[t][gw], end = g_indptr[t][gw + 1];
    if (beg >= end) return;
    float adh = g_adA[(size_t)(adoff + gw)*4 + h];
    float a0 = 0.f, a1 = 0.f, d = 0.f;
    do_edges(g_rows + eoff, beg, end,
             g_hsA + (size_t)hsoff*64, g_asA + (size_t)hsoff*4,
             lane, h, adh, a0, a1, d);
    float inv = 1.f / (d + 1e-16f);
    o0 += a0 * inv;
    o1 += a1 * inv;
}

// ---------------------------------------------------------------------------
// merged aggregation: warps [0,NU) user nodes, [NU,NU+NA) article nodes.
// bodies = R12-proven.
// ---------------------------------------------------------------------------
__global__ void k_aggr_all(int e0, int e1, int e2, int e3, int e5, int e7,
                           const float* __restrict__ bias, int l){
    int gwid = (blockIdx.x * blockDim.x + threadIdx.x) >> 5;
    int lane = threadIdx.x & 31, h = lane >> 3;
    int c0 = 2*lane, c1 = 2*lane + 1;
    const float* bl = bias + l*512;

    if (gwid < NU){
        int gw = gwid;
        float o0 = bl[64+c0] + bl[128+c0] + bl[192+c0] + bl[448+c0];
        float o1 = bl[64+c1] + bl[128+c1] + bl[192+c1] + bl[448+c1];
        aggr_one(1, gw, e1, 200000,  100000, lane, h, o0, o1);
        aggr_one(2, gw, e2, 300000,  300000, lane, h, o0, o1);
        aggr_one(3, gw, e3, 500000,  500000, lane, h, o0, o1);
        aggr_one(7, gw, e7, 1000500, 800000, lane, h, o0, o1);
        float v0 = o0 > 0.f ? o0 : 0.01f*o0;
        float v1 = o1 > 0.f ? o1 : 0.01f*o1;
        *(float2*)&g_xu[(size_t)gw*64 + c0] = make_float2(v0, v1);
        float2 au = *(float2*)&g_accu[(size_t)gw*64 + c0];
        au.x += v0; au.y += v1;
        *(float2*)&g_accu[(size_t)gw*64 + c0] = au;
    } else if (gwid < NU + NA){
        int gw = gwid - NU;
        float o0 = bl[0+c0] + bl[320+c0];
        float o1 = bl[0+c1] + bl[320+c1];
        aggr_one(0, gw, e0, 0,      0,      lane, h, o0, o1);
        aggr_one(5, gw, e5, 800000, 700000, lane, h, o0, o1);
        float v0 = o0 > 0.f ? o0 : 0.01f*o0;
        float v1 = o1 > 0.f ? o1 : 0.01f*o1;
        *(float2*)&g_xa[(size_t)gw*64 + c0] = make_float2(v0, v1);
        float2 au = *(float2*)&g_acci[(size_t)gw*64 + c0];
        au.x += v0; au.y += v1;
        *(float2*)&g_acci[(size_t)gw*64 + c0] = au;
    }
}

// ---------------------------------------------------------------------------
// merged category aggregation: t4 chunks first, then t6 chunks.
// ---------------------------------------------------------------------------
#define CCHUNK 64
__device__ __forceinline__ void cat_chunks(int t, int eoff, int E, int hsoff,
                                           const float* __restrict__ adc,
                                           float* __restrict__ tmpc,
                                           float* __restrict__ denc,
                                           int w, int lane){
    int es = w * CCHUNK;
    if (es >= E) return;
    int ee = min(es + CCHUNK, E);
    const int* __restrict__ ip = g_indptr[t];
    int lo = 0, hi = NC;
    while (lo < hi){
        int mid = (lo + hi + 1) >> 1;
        if (ip[mid] <= es) lo = mid; else hi = mid - 1;
    }
    int n = lo;
    int h = lane >> 3;
    int c0 = 2*lane;
    const int* rows = g_rows + eoff;
    const __half* hs = g_hsA + (size_t)hsoff*64;
    const float* as = g_asA + (size_t)hsoff*4;

    while (es < ee){
        int segend = min(ip[n + 1], ee);
        float adh = adc[n*4 + h];
        float a0 = 0.f, a1 = 0.f, d = 0.f;
        do_edges(rows, es, segend, hs, as, lane, h, adh, a0, a1, d);
        atomicAdd(&tmpc[n*64 + c0],     a0);
        atomicAdd(&tmpc[n*64 + c0 + 1], a1);
        if ((lane & 7) == 0)
            atomicAdd(&denc[n*4 + h], d);
        es = segend;
        n++;
    }
}

__global__ void k_aggr_cat_all(int eoff4, int E4, int eoff6, int E6){
    int w = (blockIdx.x * blockDim.x + threadIdx.x) >> 5;
    int lane = threadIdx.x & 31;
    int ch4 = (E4 + CCHUNK - 1) / CCHUNK;
    if (w < ch4){
        cat_chunks(4, eoff4, E4, 700000, g_adc4, g_tmpc0, g_denc0, w, lane);
    } else {
        cat_chunks(6, eoff6, E6, 800500, g_adc6, g_tmpc1, g_denc1, w - ch4, lane);
    }
}

// cat finalize: x_c = leaky(t4/den0 + t6/den1 + bias4 + bias6)
__global__ void k_cat_final(const float* __restrict__ bias, int l){
    int i = blockIdx.x * blockDim.x + threadIdx.x;
    if (i >= NC*DD) return;
    int n = i >> 6, c = i & 63, h = c >> 4;
    const float* bl = bias + l*512;
    float v = g_tmpc0[i] / (g_denc0[n*4 + h] + 1e-16f)
            + g_tmpc1[i] / (g_denc1[n*4 + h] + 1e-16f)
            + bl[256 + c] + bl[384 + c];
    g_xc[i] = v > 0.f ? v : 0.01f*v;
}

// ---------------------------------------------------------------------------
__global__ void k_final(float* __restrict__ out){
    int i = blockIdx.x * blockDim.x + threadIdx.x;
    const int nu = NU * DD;
    const int tot = nu + NA * DD;
    if (i >= tot) return;
    const float s = 1.f / 3.f;
    out[i] = (i < nu) ? g_accu[i] * s : g_acci[i - nu] * s;
}

// ---------------------------------------------------------------------------
static inline int cdiv(long long a, int b){ return (int)((a + b - 1) / b); }

extern "C" void kernel_launch(void* const* d_in, const int* in_sizes, int n_in,
                              void* d_out, int out_size){
    const float* x_user    = (const float*)d_in[0];
    const float* x_article = (const float*)d_in[1];
    const float* x_cat     = (const float*)d_in[2];
    const float* Wsrc      = (const float*)d_in[3];
    const float* Wdst      = (const float*)d_in[4];
    const float* att_src   = (const float*)d_in[5];
    const float* att_dst   = (const float*)d_in[6];
    const float* bias      = (const float*)d_in[7];
    float* out = (float*)d_out;

    cudaFuncSetAttribute(k_gemm_all, cudaFuncAttributeMaxDynamicSharedMemorySize, GEMM_SMEM);

    int EN[8], CUM[9]; CUM[0] = 0;
    for (int t = 0; t < 8; t++){ EN[t] = in_sizes[8 + t] / 2; CUM[t+1] = CUM[t] + EN[t]; }
    const int* EP[8];
    for (int t = 0; t < 8; t++) EP[t] = (const int*)d_in[8 + t];

    const int TOTN = (NU + NA + NC) * DD;

    // #1 init, #2 count, #3 scan1
    k_init     <<<cdiv(TOTN, 256), 256>>>(x_user, x_article, x_cat);
    k_count_all<<<cdiv(CUM[8], 256), 256>>>(EP[0],EP[1],EP[2],EP[3],EP[4],EP[5],EP[6],EP[7],
                                            CUM[1],CUM[2],CUM[3],CUM[4],CUM[5],CUM[6],CUM[7],CUM[8]);
    k_scan1    <<<NBLK_SCAN, 1024>>>();
    // #4 PROFILED: batched layer-0 GEMM (needs only k_init)
    k_gemm_all <<<GEMM_BLOCKS, 256, GEMM_SMEM>>>(Wsrc, att_src, 0);
    // #5-#7 finish CSR
    k_scan2    <<<1, 256>>>();
    k_scan3    <<<cdiv(8*(NU+1), 256), 256>>>(EN[0],EN[1],EN[2],EN[3],EN[4],EN[5],EN[6],EN[7]);
    k_fill_all <<<cdiv(CUM[8], 256), 256>>>(EP[0],EP[1],EP[2],EP[3],EP[4],EP[5],EP[6],EP[7],
                                            CUM[1],CUM[2],CUM[3],CUM[4],CUM[5],CUM[6],CUM[7],CUM[8]);

    for (int l = 0; l < 2; l++){
        if (l > 0)
            k_gemm_all<<<GEMM_BLOCKS, 256, GEMM_SMEM>>>(Wsrc, att_src, l);
        k_ad_all <<<3125 + 1563, 256>>>(Wdst, att_dst, l);
        k_ad_cat <<<cdiv(NC, 64), 256>>>(Wdst, att_dst, l);
        k_aggr_all<<<cdiv(NU + NA, 8), 256>>>(CUM[0], CUM[1], CUM[2], CUM[3],
                                              CUM[5], CUM[7], bias, l);
        {
            int ch = cdiv(EN[4], CCHUNK) + cdiv(EN[6], CCHUNK);
            k_aggr_cat_all<<<cdiv(ch, 8), 256>>>(CUM[4], EN[4], CUM[6], EN[6]);
        }
        k_cat_final<<<cdiv(NC*DD, 256), 256>>>(bias, l);
    }

    k_final<<<cdiv((long long)(NU + NA) * DD, 256), 256>>>(out);
}

// round 15
// speedup vs baseline: 1.2787x; 1.0380x over previous
#include <cuda_runtime.h>
#include <cuda_fp16.h>

// ---------------------------------------------------------------------------
// MAHGN R15: R14 + packed fp32x2 FMA (fma.rn.f32x2) GEMM inner loop —
// halves fma-pipe ops per k-step. All other kernels byte-identical to R14.
// ---------------------------------------------------------------------------

#define NU 200000
#define NA 100000
#define NC 500
#define DD 64
#define MAXE 4400000
#define TOTROWS 1001000

__constant__ int c_nd[8]   = {NA, NU, NU, NU, NC, NA, NC, NU};
__constant__ int c_boff[8] = {0, 98, 294, 490, 686, 687, 785, 786};
#define NBLK_SCAN 982
#define GEMM_SMEM (16384 + 33280)

__constant__ int gb_cum[9]   = {0, 1563, 2345, 3908, 5471, 6253, 6257, 7820, 7824};
__constant__ int gb_src[8]   = {0, 1, 0, 0, 1, 2, 0, 2};
__constant__ int gb_n[8]     = {NU, NA, NU, NU, NA, NC, NU, NC};
__constant__ int gb_hsoff[8] = {0, 200000, 300000, 500000, 700000, 800000, 800500, 1000500};
#define GEMM_BLOCKS 7824

// features / accumulators
__device__ float  g_xu[NU*DD], g_xa[NA*DD], g_xc[NC*DD];
__device__ __half g_hsA[(size_t)TOTROWS*DD];
__device__ float  g_asA[TOTROWS*4];
__device__ float  g_adA[1000000*4];
__device__ float  g_adc4[NC*4], g_adc6[NC*4];
__device__ float  g_accu[NU*DD], g_acci[NA*DD];
__device__ float  g_tmpc0[NC*DD], g_tmpc1[NC*DD], g_denc0[NC*4], g_denc1[NC*4];

// CSR scratch
__device__ int g_cnt8[8][NU];
__device__ int g_cur8[8][NU];
__device__ int g_indptr[8][NU+1];
__device__ int g_bsum[1024];
__device__ int g_rows[MAXE];

__device__ __forceinline__ float* xp(int s){ return s==0 ? g_xu : (s==1 ? g_xa : g_xc); }

// ---- packed f32x2 helpers ----
__device__ __forceinline__ unsigned long long pk2(float lo, float hi){
    unsigned long long r;
    asm("mov.b64 %0, {%1,%2};" : "=l"(r) : "f"(lo), "f"(hi));
    return r;
}
__device__ __forceinline__ void upk2(unsigned long long v, float& lo, float& hi){
    asm("mov.b64 {%0,%1}, %2;" : "=f"(lo), "=f"(hi) : "l"(v));
}
__device__ __forceinline__ void fma2(unsigned long long& c,
                                     unsigned long long a, unsigned long long b){
    asm("fma.rn.f32x2 %0, %1, %2, %3;" : "=l"(c) : "l"(a), "l"(b), "l"(c));
}

// ---------------------------------------------------------------------------
__global__ void k_init(const float* __restrict__ xu, const float* __restrict__ xa,
                       const float* __restrict__ xc){
    int i = blockIdx.x * blockDim.x + threadIdx.x;
    if (i < 8*NU) ((int*)g_cnt8)[i] = 0;
    if (i < NU*DD){
        float v = xu[i]; g_xu[i] = v; g_accu[i] = v;
    } else if (i < (NU+NA)*DD){
        int j = i - NU*DD;
        float v = xa[j]; g_xa[j] = v; g_acci[j] = v;
    } else if (i < (NU+NA+NC)*DD){
        int j = i - (NU+NA)*DD;
        g_xc[j] = xc[j];
    }
}

// ---------------------------------------------------------------------------
// CSR build (proven)
// ---------------------------------------------------------------------------
#define PICK_TYPE \
    const int* ei; int base, next, t; \
    if      (i < c1){ ei = e0; base = 0;  next = c1; t = 0; } \
    else if (i < c2){ ei = e1; base = c1; next = c2; t = 1; } \
    else if (i < c3){ ei = e2; base = c2; next = c3; t = 2; } \
    else if (i < c4){ ei = e3; base = c3; next = c4; t = 3; } \
    else if (i < c5){ ei = e4; base = c4; next = c5; t = 4; } \
    else if (i < c6){ ei = e5; base = c5; next = c6; t = 5; } \
    else if (i < c7){ ei = e6; base = c6; next = c7; t = 6; } \
    else            { ei = e7; base = c7; next = cT; t = 7; } \
    int E = next - base, local = i - base;

__global__ void k_count_all(const int* e0,const int* e1,const int* e2,const int* e3,
                            const int* e4,const int* e5,const int* e6,const int* e7,
                            int c1,int c2,int c3,int c4,int c5,int c6,int c7,int cT){
    int i = blockIdx.x * blockDim.x + threadIdx.x;
    if (i >= cT) return;
    PICK_TYPE
    atomicAdd(&g_cnt8[t][ei[E + local]], 1);
}

__global__ void k_scan1(){
    __shared__ int wsum[32];
    int b = blockIdx.x, tid = threadIdx.x, lane = tid & 31, wid = tid >> 5;
    int t;
    if      (b < 98)  t = 0;
    else if (b < 294) t = 1;
    else if (b < 490) t = 2;
    else if (b < 686) t = 3;
    else if (b < 687) t = 4;
    else if (b < 785) t = 5;
    else if (b < 786) t = 6;
    else              t = 7;
    int i = (b - c_boff[t]) * 1024 + tid;
    int nd = c_nd[t];
    int v = (i < nd) ? g_cnt8[t][i] : 0;
    int x = v;
#pragma unroll
    for (int o = 1; o < 32; o <<= 1){
        int y = __shfl_up_sync(0xffffffffu, x, o);
        if (lane >= o) x += y;
    }
    if (lane == 31) wsum[wid] = x;
    __syncthreads();
    if (wid == 0){
        int s = wsum[lane];
#pragma unroll
        for (int o = 1; o < 32; o <<= 1){
            int y = __shfl_up_sync(0xffffffffu, s, o);
            if (lane >= o) s += y;
        }
        wsum[lane] = s;
    }
    __syncthreads();
    int excl = (x - v) + (wid ? wsum[wid - 1] : 0);
    if (i < nd) g_indptr[t][i] = excl;
    if (tid == 0) g_bsum[b] = wsum[31];
}

__global__ void k_scan2(){
    int w = threadIdx.x >> 5, lane = threadIdx.x & 31;
    if (w >= 8) return;
    const int nbs[8] = {98, 196, 196, 196, 1, 98, 1, 196};
    int off = c_boff[w], nb = nbs[w];
    int carry = 0;
    for (int base = 0; base < nb; base += 32){
        int i = base + lane;
        int v = (i < nb) ? g_bsum[off + i] : 0;
        int x = v;
#pragma unroll
        for (int o = 1; o < 32; o <<= 1){
            int y = __shfl_up_sync(0xffffffffu, x, o);
            if (lane >= o) x += y;
        }
        if (i < nb) g_bsum[off + i] = x - v + carry;
        carry += __shfl_sync(0xffffffffu, x, 31);
    }
}

__global__ void k_scan3(int e0n,int e1n,int e2n,int e3n,int e4n,int e5n,int e6n,int e7n){
    int i = blockIdx.x * blockDim.x + threadIdx.x;
    if (i >= 8*(NU+1)) return;
    int t = i / (NU+1), j = i - t*(NU+1);
    int nd = c_nd[t];
    if (j < nd){
        int v = g_indptr[t][j] + g_bsum[c_boff[t] + (j >> 10)];
        g_indptr[t][j] = v;
        g_cur8[t][j] = v;
    } else if (j == nd){
        const int ens[8] = {e0n,e1n,e2n,e3n,e4n,e5n,e6n,e7n};
        g_indptr[t][nd] = ens[t];
    }
}

__global__ void k_fill_all(const int* e0,const int* e1,const int* e2,const int* e3,
                           const int* e4,const int* e5,const int* e6,const int* e7,
                           int c1,int c2,int c3,int c4,int c5,int c6,int c7,int cT){
    int i = blockIdx.x * blockDim.x + threadIdx.x;
    if (i >= cT) return;
    PICK_TYPE
    int row = ei[local];
    int col = ei[E + local];
    int pos = atomicAdd(&g_cur8[t][col], 1);
    g_rows[base + pos] = row;
}

// ---------------------------------------------------------------------------
// Batched GEMM, f32x2 inner loop (math bit-identical fp32 FMA per lane)
// ---------------------------------------------------------------------------
__global__ void k_gemm_all(const float* __restrict__ Wsrc,
                           const float* __restrict__ att_src, int l){
    extern __shared__ float dsm[];
    float* sW = dsm;
    float* sX = dsm + 4096;
    int b = blockIdx.x;
    int t = 0;
#pragma unroll
    for (int q = 1; q < 8; q++) if (b >= gb_cum[q]) t = q;
    int src_sel = gb_src[t];
    int N = gb_n[t];
    const float* x = xp(src_sel);
    const float* W   = Wsrc    + (size_t)(l*8 + t) * 4096;
    const float* att = att_src + (size_t)(l*8 + t) * 64;
    __half* hs = g_hsA + (size_t)gb_hsoff[t] * 64;
    float*  as = g_asA + (size_t)gb_hsoff[t] * 4;
    int tid = threadIdx.x;

    for (int i = tid; i < 1024; i += 256)
        ((float4*)sW)[i] = ((const float4*)W)[i];

    int row0 = (b - gb_cum[t]) * 128;
    for (int i = tid; i < 2048; i += 256){
        int r = i >> 4, c4 = i & 15;
        int gr = row0 + r;
        float4 v = (gr < N) ? ((const float4*)x)[(size_t)gr*16 + c4]
                            : make_float4(0.f, 0.f, 0.f, 0.f);
        sX[r*65 + c4*4+0] = v.x; sX[r*65 + c4*4+1] = v.y;
        sX[r*65 + c4*4+2] = v.z; sX[r*65 + c4*4+3] = v.w;
    }
    __syncthreads();

    int rp = tid >> 3, cg = tid & 7;
    int r0 = rp * 4;
    int cA = cg * 4, cB = 32 + cg * 4;
    float4 attA = __ldg((const float4*)&att[cA]);
    float4 attB = __ldg((const float4*)&att[cB]);

    // packed accumulators: acc2[i][p] = pair (col 2p, col 2p+1) of the 8 cols
    unsigned long long acc2[4][4];
#pragma unroll
    for (int i = 0; i < 4; i++)
#pragma unroll
        for (int p = 0; p < 4; p++) acc2[i][p] = 0ULL;

#pragma unroll 8
    for (int k = 0; k < 64; k++){
        float4 w0 = *(const float4*)&sW[k*64 + cA];
        float4 w1 = *(const float4*)&sW[k*64 + cB];
        unsigned long long wp0 = pk2(w0.x, w0.y);
        unsigned long long wp1 = pk2(w0.z, w0.w);
        unsigned long long wp2 = pk2(w1.x, w1.y);
        unsigned long long wp3 = pk2(w1.z, w1.w);
#pragma unroll
        for (int i = 0; i < 4; i++){
            float xv = sX[(r0 + i)*65 + k];
            unsigned long long xv2 = pk2(xv, xv);
            fma2(acc2[i][0], xv2, wp0);
            fma2(acc2[i][1], xv2, wp1);
            fma2(acc2[i][2], xv2, wp2);
            fma2(acc2[i][3], xv2, wp3);
        }
    }

#pragma unroll
    for (int i = 0; i < 4; i++){
        float a0,a1,a2,a3,a4,a5,a6,a7;
        upk2(acc2[i][0], a0, a1);
        upk2(acc2[i][1], a2, a3);
        upk2(acc2[i][2], a4, a5);
        upk2(acc2[i][3], a6, a7);
        int gr = row0 + r0 + i;
        float pA = a0*attA.x + a1*attA.y + a2*attA.z + a3*attA.w;
        float pB = a4*attB.x + a5*attB.y + a6*attB.z + a7*attB.w;
        pA += __shfl_xor_sync(0xffffffffu, pA, 1);
        pA += __shfl_xor_sync(0xffffffffu, pA, 2);
        pB += __shfl_xor_sync(0xffffffffu, pB, 1);
        pB += __shfl_xor_sync(0xffffffffu, pB, 2);
        if (gr < N){
            union { __half2 h2[2]; uint2 u; } pk;
            pk.h2[0] = __floats2half2_rn(a0, a1);
            pk.h2[1] = __floats2half2_rn(a2, a3);
            *(uint2*)&hs[(size_t)gr*64 + cA] = pk.u;
            pk.h2[0] = __floats2half2_rn(a4, a5);
            pk.h2[1] = __floats2half2_rn(a6, a7);
            *(uint2*)&hs[(size_t)gr*64 + cB] = pk.u;
            if ((cg & 3) == 0){
                int h01 = cg >> 2;
                as[gr*4 + h01]     = pA;
                as[gr*4 + 2 + h01] = pB;
            }
        }
    }
}

// ---------------------------------------------------------------------------
// merged a_d: user dst (t1,t2,t3,t7) blocks [0,3125), article (t0,t5) after.
// ---------------------------------------------------------------------------
__global__ void k_ad_all(const float* __restrict__ Wdst,
                         const float* __restrict__ attd, int l){
    __shared__ float sWd[4][64][4];
    __shared__ float sX[64][65];
    int b = blockIdx.x;
    int dst_sel, N, nT, row0;
    int tl[4], dofs[4];
    if (b < 3125){
        dst_sel = 0; N = NU; nT = 4; row0 = b * 64;
        tl[0]=1; tl[1]=2; tl[2]=3; tl[3]=7;
        dofs[0]=100000; dofs[1]=300000; dofs[2]=500000; dofs[3]=800000;
    } else {
        dst_sel = 1; N = NA; nT = 2; row0 = (b - 3125) * 64;
        tl[0]=0; tl[1]=5; tl[2]=0; tl[3]=0;
        dofs[0]=0; dofs[1]=700000; dofs[2]=0; dofs[3]=0;
    }
    const float* x = xp(dst_sel);
    int tid = threadIdx.x;

    {
        int k = tid >> 2, h = tid & 3;
#pragma unroll
        for (int q = 0; q < 4; q++){
            if (q < nT){
                const float* Wd = Wdst + (size_t)(l*8 + tl[q]) * 4096;
                const float* at = attd + (size_t)(l*8 + tl[q]) * 64;
                float s = 0.f;
#pragma unroll
                for (int c = 0; c < 16; c++) s += Wd[k*64 + h*16 + c] * at[h*16 + c];
                sWd[q][k][h] = s;
            }
        }
    }
    for (int i = tid; i < 4096; i += 256){
        int r = i >> 6, c = i & 63;
        int gr = row0 + r;
        sX[r][c] = (gr < N) ? x[gr*64 + c] : 0.f;
    }
    __syncthreads();

    int r = tid >> 2, h = tid & 3;
    int gr = row0 + r;
    if (gr < N){
#pragma unroll
        for (int q = 0; q < 4; q++){
            if (q < nT){
                float s = 0.f;
#pragma unroll
                for (int k = 0; k < 64; k++) s += sX[r][k] * sWd[q][k][h];
                g_adA[(size_t)(dofs[q] + gr)*4 + h] = s;
            }
        }
    }
}

// ---------------------------------------------------------------------------
// merged cat a_d: t4 and t6 folded vectors; also zero partial buffers.
// ---------------------------------------------------------------------------
__global__ void k_ad_cat(const float* __restrict__ Wdst,
                         const float* __restrict__ attd, int l){
    __shared__ float sWd[2][64][4];
    __shared__ float sX[64][65];
    int tid = threadIdx.x;
    const int tl[2] = {4, 6};
    {
        int k = tid >> 2, h = tid & 3;
#pragma unroll
        for (int q = 0; q < 2; q++){
            const float* Wd = Wdst + (size_t)(l*8 + tl[q]) * 4096;
            const float* at = attd + (size_t)(l*8 + tl[q]) * 64;
            float s = 0.f;
#pragma unroll
            for (int c = 0; c < 16; c++) s += Wd[k*64 + h*16 + c] * at[h*16 + c];
            sWd[q][k][h] = s;
        }
    }
    int row0 = blockIdx.x * 64;
    for (int i = tid; i < 4096; i += 256){
        int r = i >> 6, c = i & 63;
        int gr = row0 + r;
        sX[r][c] = (gr < NC) ? g_xc[gr*64 + c] : 0.f;
    }
    __syncthreads();

    int r = tid >> 2, h = tid & 3;
    int gr = row0 + r;
    if (gr < NC){
        float s4 = 0.f, s6 = 0.f;
#pragma unroll
        for (int k = 0; k < 64; k++){
            float xv = sX[r][k];
            s4 += xv * sWd[0][k][h];
            s6 += xv * sWd[1][k][h];
        }
        g_adc4[gr*4 + h] = s4;
        g_adc6[gr*4 + h] = s6;
        g_denc0[gr*4 + h] = 0.f;
        g_denc1[gr*4 + h] = 0.f;
        float4 z = make_float4(0.f,0.f,0.f,0.f);
        float4* t0 = (float4*)&g_tmpc0[gr*64 + h*16];
        float4* t1 = (float4*)&g_tmpc1[gr*64 + h*16];
        t0[0]=z; t0[1]=z; t0[2]=z; t0[3]=z;
        t1[0]=z; t1[1]=z; t1[2]=z; t1[3]=z;
    }
}

// ---------------------------------------------------------------------------
// edge segment body, half2 layout (R12-proven)
// ---------------------------------------------------------------------------
__device__ __forceinline__ void do_edges(const int* __restrict__ rows, int beg, int end,
                                         const __half* __restrict__ hs,
                                         const float* __restrict__ as,
                                         int lane, int h, float adh,
                                         float& a0, float& a1, float& d){
    const __half2* hs2 = (const __half2*)hs;
    int e = beg;
    for (; e + 4 <= end; e += 4){
        int r0 = __ldg(rows + e + 0), r1 = __ldg(rows + e + 1);
        int r2 = __ldg(rows + e + 2), r3 = __ldg(rows + e + 3);
        float s0 = __ldg(&as[r0*4 + h]);
        float s1 = __ldg(&as[r1*4 + h]);
        float s2 = __ldg(&as[r2*4 + h]);
        float s3 = __ldg(&as[r3*4 + h]);
        __half2 u0 = __ldg(&hs2[(size_t)r0*32 + lane]);
        __half2 u1 = __ldg(&hs2[(size_t)r1*32 + lane]);
        __half2 u2 = __ldg(&hs2[(size_t)r2*32 + lane]);
        __half2 u3 = __ldg(&hs2[(size_t)r3*32 + lane]);

        float e0 = s0 + adh, e1 = s1 + adh, e2 = s2 + adh, e3 = s3 + adh;
        e0 = e0 > 0.f ? e0 : 0.2f*e0;
        e1 = e1 > 0.f ? e1 : 0.2f*e1;
        e2 = e2 > 0.f ? e2 : 0.2f*e2;
        e3 = e3 > 0.f ? e3 : 0.2f*e3;
        float x0 = __expf(e0), x1 = __expf(e1), x2 = __expf(e2), x3 = __expf(e3);

        float2 f0 = __half22float2(u0);
        float2 f1 = __half22float2(u1);
        float2 f2 = __half22float2(u2);
        float2 f3 = __half22float2(u3);
        a0 += x0*f0.x + x1*f1.x + x2*f2.x + x3*f3.x;
        a1 += x0*f0.y + x1*f1.y + x2*f2.y + x3*f3.y;
        d  += x0 + x1 + x2 + x3;
    }
    for (; e < end; e++){
        int row = __ldg(rows + e);
        float ev = __ldg(&as[row*4 + h]) + adh;
        ev = ev > 0.f ? ev : 0.2f*ev;
        float ex = __expf(ev);
        float2 f = __half22float2(__ldg(&hs2[(size_t)row*32 + lane]));
        a0 += ex*f.x; a1 += ex*f.y; d += ex;
    }
}

__device__ __forceinline__ void aggr_one(int t, int gw, int eoff, int hsoff, int adoff,
                                         int lane, int h, float& o0, float& o1){
    int beg = g_indptr[t][gw], end = g_indptr[t][gw + 1];
    if (beg >= end) return;
    float adh = g_adA[(size_t)(adoff + gw)*4 + h];
    float a0 = 0.f, a1 = 0.f, d = 0.f;
    do_edges(g_rows + eoff, beg, end,
             g_hsA + (size_t)hsoff*64, g_asA + (size_t)hsoff*4,
             lane, h, adh, a0, a1, d);
    float inv = 1.f / (d + 1e-16f);
    o0 += a0 * inv;
    o1 += a1 * inv;
}

// ---------------------------------------------------------------------------
// merged aggregation: warps [0,NU) user nodes, [NU,NU+NA) article nodes.
// ---------------------------------------------------------------------------
__global__ void k_aggr_all(int e0, int e1, int e2, int e3, int e5, int e7,
                           const float* __restrict__ bias, int l){
    int gwid = (blockIdx.x * blockDim.x + threadIdx.x) >> 5;
    int lane = threadIdx.x & 31, h = lane >> 3;
    int c0 = 2*lane, c1 = 2*lane + 1;
    const float* bl = bias + l*512;

    if (gwid < NU){
        int gw = gwid;
        float o0 = bl[64+c0] + bl[128+c0] + bl[192+c0] + bl[448+c0];
        float o1 = bl[64+c1] + bl[128+c1] + bl[192+c1] + bl[448+c1];
        aggr_one(1, gw, e1, 200000,  100000, lane, h, o0, o1);
        aggr_one(2, gw, e2, 300000,  300000, lane, h, o0, o1);
        aggr_one(3, gw, e3, 500000,  500000, lane, h, o0, o1);
        aggr_one(7, gw, e7, 1000500, 800000, lane, h, o0, o1);
        float v0 = o0 > 0.f ? o0 : 0.01f*o0;
        float v1 = o1 > 0.f ? o1 : 0.01f*o1;
        *(float2*)&g_xu[(size_t)gw*64 + c0] = make_float2(v0, v1);
        float2 au = *(float2*)&g_accu[(size_t)gw*64 + c0];
        au.x += v0; au.y += v1;
        *(float2*)&g_accu[(size_t)gw*64 + c0] = au;
    } else if (gwid < NU + NA){
        int gw = gwid - NU;
        float o0 = bl[0+c0] + bl[320+c0];
        float o1 = bl[0+c1] + bl[320+c1];
        aggr_one(0, gw, e0, 0,      0,      lane, h, o0, o1);
        aggr_one(5, gw, e5, 800000, 700000, lane, h, o0, o1);
        float v0 = o0 > 0.f ? o0 : 0.01f*o0;
        float v1 = o1 > 0.f ? o1 : 0.01f*o1;
        *(float2*)&g_xa[(size_t)gw*64 + c0] = make_float2(v0, v1);
        float2 au = *(float2*)&g_acci[(size_t)gw*64 + c0];
        au.x += v0; au.y += v1;
        *(float2*)&g_acci[(size_t)gw*64 + c0] = au;
    }
}

// ---------------------------------------------------------------------------
// merged category aggregation
// ---------------------------------------------------------------------------
#define CCHUNK 64
__device__ __forceinline__ void cat_chunks(int t, int eoff, int E, int hsoff,
                                           const float* __restrict__ adc,
                                           float* __restrict__ tmpc,
                                           float* __restrict__ denc,
                                           int w, int lane){
    int es = w * CCHUNK;
    if (es >= E) return;
    int ee = min(es + CCHUNK, E);
    const int* __restrict__ ip = g_indptr[t];
    int lo = 0, hi = NC;
    while (lo < hi){
        int mid = (lo + hi + 1) >> 1;
        if (ip[mid] <= es) lo = mid; else hi = mid - 1;
    }
    int n = lo;
    int h = lane >> 3;
    int c0 = 2*lane;
    const int* rows = g_rows + eoff;
    const __half* hs = g_hsA + (size_t)hsoff*64;
    const float* as = g_asA + (size_t)hsoff*4;

    while (es < ee){
        int segend = min(ip[n + 1], ee);
        float adh = adc[n*4 + h];
        float a0 = 0.f, a1 = 0.f, d = 0.f;
        do_edges(rows, es, segend, hs, as, lane, h, adh, a0, a1, d);
        atomicAdd(&tmpc[n*64 + c0],     a0);
        atomicAdd(&tmpc[n*64 + c0 + 1], a1);
        if ((lane & 7) == 0)
            atomicAdd(&denc[n*4 + h], d);
        es = segend;
        n++;
    }
}

__global__ void k_aggr_cat_all(int eoff4, int E4, int eoff6, int E6){
    int w = (blockIdx.x * blockDim.x + threadIdx.x) >> 5;
    int lane = threadIdx.x & 31;
    int ch4 = (E4 + CCHUNK - 1) / CCHUNK;
    if (w < ch4){
        cat_chunks(4, eoff4, E4, 700000, g_adc4, g_tmpc0, g_denc0, w, lane);
    } else {
        cat_chunks(6, eoff6, E6, 800500, g_adc6, g_tmpc1, g_denc1, w - ch4, lane);
    }
}

__global__ void k_cat_final(const float* __restrict__ bias, int l){
    int i = blockIdx.x * blockDim.x + threadIdx.x;
    if (i >= NC*DD) return;
    int n = i >> 6, c = i & 63, h = c >> 4;
    const float* bl = bias + l*512;
    float v = g_tmpc0[i] / (g_denc0[n*4 + h] + 1e-16f)
            + g_tmpc1[i] / (g_denc1[n*4 + h] + 1e-16f)
            + bl[256 + c] + bl[384 + c];
    g_xc[i] = v > 0.f ? v : 0.01f*v;
}

// ---------------------------------------------------------------------------
__global__ void k_final(float* __restrict__ out){
    int i = blockIdx.x * blockDim.x + threadIdx.x;
    const int nu = NU * DD;
    const int tot = nu + NA * DD;
    if (i >= tot) return;
    const float s = 1.f / 3.f;
    out[i] = (i < nu) ? g_accu[i] * s : g_acci[i - nu] * s;
}

// ---------------------------------------------------------------------------
static inline int cdiv(long long a, int b){ return (int)((a + b - 1) / b); }

extern "C" void kernel_launch(void* const* d_in, const int* in_sizes, int n_in,
                              void* d_out, int out_size){
    const float* x_user    = (const float*)d_in[0];
    const float* x_article = (const float*)d_in[1];
    const float* x_cat     = (const float*)d_in[2];
    const float* Wsrc      = (const float*)d_in[3];
    const float* Wdst      = (const float*)d_in[4];
    const float* att_src   = (const float*)d_in[5];
    const float* att_dst   = (const float*)d_in[6];
    const float* bias      = (const float*)d_in[7];
    float* out = (float*)d_out;

    cudaFuncSetAttribute(k_gemm_all, cudaFuncAttributeMaxDynamicSharedMemorySize, GEMM_SMEM);

    int EN[8], CUM[9]; CUM[0] = 0;
    for (int t = 0; t < 8; t++){ EN[t] = in_sizes[8 + t] / 2; CUM[t+1] = CUM[t] + EN[t]; }
    const int* EP[8];
    for (int t = 0; t < 8; t++) EP[t] = (const int*)d_in[8 + t];

    const int TOTN = (NU + NA + NC) * DD;

    k_init     <<<cdiv(TOTN, 256), 256>>>(x_user, x_article, x_cat);
    k_count_all<<<cdiv(CUM[8], 256), 256>>>(EP[0],EP[1],EP[2],EP[3],EP[4],EP[5],EP[6],EP[7],
                                            CUM[1],CUM[2],CUM[3],CUM[4],CUM[5],CUM[6],CUM[7],CUM[8]);
    k_scan1    <<<NBLK_SCAN, 1024>>>();
    // #4 PROFILED: batched layer-0 GEMM
    k_gemm_all <<<GEMM_BLOCKS, 256, GEMM_SMEM>>>(Wsrc, att_src, 0);
    k_scan2    <<<1, 256>>>();
    k_scan3    <<<cdiv(8*(NU+1), 256), 256>>>(EN[0],EN[1],EN[2],EN[3],EN[4],EN[5],EN[6],EN[7]);
    k_fill_all <<<cdiv(CUM[8], 256), 256>>>(EP[0],EP[1],EP[2],EP[3],EP[4],EP[5],EP[6],EP[7],
                                            CUM[1],CUM[2],CUM[3],CUM[4],CUM[5],CUM[6],CUM[7],CUM[8]);

    for (int l = 0; l < 2; l++){
        if (l > 0)
            k_gemm_all<<<GEMM_BLOCKS, 256, GEMM_SMEM>>>(Wsrc, att_src, l);
        k_ad_all <<<3125 + 1563, 256>>>(Wdst, att_dst, l);
        k_ad_cat <<<cdiv(NC, 64), 256>>>(Wdst, att_dst, l);
        k_aggr_all<<<cdiv(NU + NA, 8), 256>>>(CUM[0], CUM[1], CUM[2], CUM[3],
                                              CUM[5], CUM[7], bias, l);
        {
            int ch = cdiv(EN[4], CCHUNK) + cdiv(EN[6], CCHUNK);
            k_aggr_cat_all<<<cdiv(ch, 8), 256>>>(CUM[4], EN[4], CUM[6], EN[6]);
        }
        k_cat_final<<<cdiv(NC*DD, 256), 256>>>(bias, l);
    }

    k_final<<<cdiv((long long)(NU + NA) * DD, 256), 256>>>(out);
}

// round 16
// speedup vs baseline: 1.2928x; 1.0110x over previous
#include <cuda_runtime.h>
#include <cuda_fp16.h>

// ---------------------------------------------------------------------------
// MAHGN R16: R15 with GEMM inner-loop micro-fixes: (a) W pairs loaded
// directly from smem as ulonglong2 (two adjacent fp32 ARE a packed f32x2 —
// zero mov.b64), (b) __launch_bounds__(256,4) for 4 blocks/SM occupancy.
// All other kernels byte-identical to R15.
// ---------------------------------------------------------------------------

#define NU 200000
#define NA 100000
#define NC 500
#define DD 64
#define MAXE 4400000
#define TOTROWS 1001000

__constant__ int c_nd[8]   = {NA, NU, NU, NU, NC, NA, NC, NU};
__constant__ int c_boff[8] = {0, 98, 294, 490, 686, 687, 785, 786};
#define NBLK_SCAN 982
#define GEMM_SMEM (16384 + 33280)

__constant__ int gb_cum[9]   = {0, 1563, 2345, 3908, 5471, 6253, 6257, 7820, 7824};
__constant__ int gb_src[8]   = {0, 1, 0, 0, 1, 2, 0, 2};
__constant__ int gb_n[8]     = {NU, NA, NU, NU, NA, NC, NU, NC};
__constant__ int gb_hsoff[8] = {0, 200000, 300000, 500000, 700000, 800000, 800500, 1000500};
#define GEMM_BLOCKS 7824

// features / accumulators
__device__ float  g_xu[NU*DD], g_xa[NA*DD], g_xc[NC*DD];
__device__ __half g_hsA[(size_t)TOTROWS*DD];
__device__ float  g_asA[TOTROWS*4];
__device__ float  g_adA[1000000*4];
__device__ float  g_adc4[NC*4], g_adc6[NC*4];
__device__ float  g_accu[NU*DD], g_acci[NA*DD];
__device__ float  g_tmpc0[NC*DD], g_tmpc1[NC*DD], g_denc0[NC*4], g_denc1[NC*4];

// CSR scratch
__device__ int g_cnt8[8][NU];
__device__ int g_cur8[8][NU];
__device__ int g_indptr[8][NU+1];
__device__ int g_bsum[1024];
__device__ int g_rows[MAXE];

__device__ __forceinline__ float* xp(int s){ return s==0 ? g_xu : (s==1 ? g_xa : g_xc); }

// ---- packed f32x2 helpers ----
__device__ __forceinline__ unsigned long long pk2(float lo, float hi){
    unsigned long long r;
    asm("mov.b64 %0, {%1,%2};" : "=l"(r) : "f"(lo), "f"(hi));
    return r;
}
__device__ __forceinline__ void upk2(unsigned long long v, float& lo, float& hi){
    asm("mov.b64 {%0,%1}, %2;" : "=f"(lo), "=f"(hi) : "l"(v));
}
__device__ __forceinline__ void fma2(unsigned long long& c,
                                     unsigned long long a, unsigned long long b){
    asm("fma.rn.f32x2 %0, %1, %2, %3;" : "=l"(c) : "l"(a), "l"(b), "l"(c));
}

// ---------------------------------------------------------------------------
__global__ void k_init(const float* __restrict__ xu, const float* __restrict__ xa,
                       const float* __restrict__ xc){
    int i = blockIdx.x * blockDim.x + threadIdx.x;
    if (i < 8*NU) ((int*)g_cnt8)[i] = 0;
    if (i < NU*DD){
        float v = xu[i]; g_xu[i] = v; g_accu[i] = v;
    } else if (i < (NU+NA)*DD){
        int j = i - NU*DD;
        float v = xa[j]; g_xa[j] = v; g_acci[j] = v;
    } else if (i < (NU+NA+NC)*DD){
        int j = i - (NU+NA)*DD;
        g_xc[j] = xc[j];
    }
}

// ---------------------------------------------------------------------------
// CSR build (proven)
// ---------------------------------------------------------------------------
#define PICK_TYPE \
    const int* ei; int base, next, t; \
    if      (i < c1){ ei = e0; base = 0;  next = c1; t = 0; } \
    else if (i < c2){ ei = e1; base = c1; next = c2; t = 1; } \
    else if (i < c3){ ei = e2; base = c2; next = c3; t = 2; } \
    else if (i < c4){ ei = e3; base = c3; next = c4; t = 3; } \
    else if (i < c5){ ei = e4; base = c4; next = c5; t = 4; } \
    else if (i < c6){ ei = e5; base = c5; next = c6; t = 5; } \
    else if (i < c7){ ei = e6; base = c6; next = c7; t = 6; } \
    else            { ei = e7; base = c7; next = cT; t = 7; } \
    int E = next - base, local = i - base;

__global__ void k_count_all(const int* e0,const int* e1,const int* e2,const int* e3,
                            const int* e4,const int* e5,const int* e6,const int* e7,
                            int c1,int c2,int c3,int c4,int c5,int c6,int c7,int cT){
    int i = blockIdx.x * blockDim.x + threadIdx.x;
    if (i >= cT) return;
    PICK_TYPE
    atomicAdd(&g_cnt8[t][ei[E + local]], 1);
}

__global__ void k_scan1(){
    __shared__ int wsum[32];
    int b = blockIdx.x, tid = threadIdx.x, lane = tid & 31, wid = tid >> 5;
    int t;
    if      (b < 98)  t = 0;
    else if (b < 294) t = 1;
    else if (b < 490) t = 2;
    else if (b < 686) t = 3;
    else if (b < 687) t = 4;
    else if (b < 785) t = 5;
    else if (b < 786) t = 6;
    else              t = 7;
    int i = (b - c_boff[t]) * 1024 + tid;
    int nd = c_nd[t];
    int v = (i < nd) ? g_cnt8[t][i] : 0;
    int x = v;
#pragma unroll
    for (int o = 1; o < 32; o <<= 1){
        int y = __shfl_up_sync(0xffffffffu, x, o);
        if (lane >= o) x += y;
    }
    if (lane == 31) wsum[wid] = x;
    __syncthreads();
    if (wid == 0){
        int s = wsum[lane];
#pragma unroll
        for (int o = 1; o < 32; o <<= 1){
            int y = __shfl_up_sync(0xffffffffu, s, o);
            if (lane >= o) s += y;
        }
        wsum[lane] = s;
    }
    __syncthreads();
    int excl = (x - v) + (wid ? wsum[wid - 1] : 0);
    if (i < nd) g_indptr[t][i] = excl;
    if (tid == 0) g_bsum[b] = wsum[31];
}

__global__ void k_scan2(){
    int w = threadIdx.x >> 5, lane = threadIdx.x & 31;
    if (w >= 8) return;
    const int nbs[8] = {98, 196, 196, 196, 1, 98, 1, 196};
    int off = c_boff[w], nb = nbs[w];
    int carry = 0;
    for (int base = 0; base < nb; base += 32){
        int i = base + lane;
        int v = (i < nb) ? g_bsum[off + i] : 0;
        int x = v;
#pragma unroll
        for (int o = 1; o < 32; o <<= 1){
            int y = __shfl_up_sync(0xffffffffu, x, o);
            if (lane >= o) x += y;
        }
        if (i < nb) g_bsum[off + i] = x - v + carry;
        carry += __shfl_sync(0xffffffffu, x, 31);
    }
}

__global__ void k_scan3(int e0n,int e1n,int e2n,int e3n,int e4n,int e5n,int e6n,int e7n){
    int i = blockIdx.x * blockDim.x + threadIdx.x;
    if (i >= 8*(NU+1)) return;
    int t = i / (NU+1), j = i - t*(NU+1);
    int nd = c_nd[t];
    if (j < nd){
        int v = g_indptr[t][j] + g_bsum[c_boff[t] + (j >> 10)];
        g_indptr[t][j] = v;
        g_cur8[t][j] = v;
    } else if (j == nd){
        const int ens[8] = {e0n,e1n,e2n,e3n,e4n,e5n,e6n,e7n};
        g_indptr[t][nd] = ens[t];
    }
}

__global__ void k_fill_all(const int* e0,const int* e1,const int* e2,const int* e3,
                           const int* e4,const int* e5,const int* e6,const int* e7,
                           int c1,int c2,int c3,int c4,int c5,int c6,int c7,int cT){
    int i = blockIdx.x * blockDim.x + threadIdx.x;
    if (i >= cT) return;
    PICK_TYPE
    int row = ei[local];
    int col = ei[E + local];
    int pos = atomicAdd(&g_cur8[t][col], 1);
    g_rows[base + pos] = row;
}

// ---------------------------------------------------------------------------
// Batched GEMM, f32x2 inner loop with zero-mov W pairs (ull2 smem loads).
// ---------------------------------------------------------------------------
__global__ void __launch_bounds__(256, 4)
k_gemm_all(const float* __restrict__ Wsrc,
           const float* __restrict__ att_src, int l){
    extern __shared__ float dsm[];
    float* sW = dsm;
    float* sX = dsm + 4096;
    int b = blockIdx.x;
    int t = 0;
#pragma unroll
    for (int q = 1; q < 8; q++) if (b >= gb_cum[q]) t = q;
    int src_sel = gb_src[t];
    int N = gb_n[t];
    const float* x = xp(src_sel);
    const float* W   = Wsrc    + (size_t)(l*8 + t) * 4096;
    const float* att = att_src + (size_t)(l*8 + t) * 64;
    __half* hs = g_hsA + (size_t)gb_hsoff[t] * 64;
    float*  as = g_asA + (size_t)gb_hsoff[t] * 4;
    int tid = threadIdx.x;

    for (int i = tid; i < 1024; i += 256)
        ((float4*)sW)[i] = ((const float4*)W)[i];

    int row0 = (b - gb_cum[t]) * 128;
    for (int i = tid; i < 2048; i += 256){
        int r = i >> 4, c4 = i & 15;
        int gr = row0 + r;
        float4 v = (gr < N) ? ((const float4*)x)[(size_t)gr*16 + c4]
                            : make_float4(0.f, 0.f, 0.f, 0.f);
        sX[r*65 + c4*4+0] = v.x; sX[r*65 + c4*4+1] = v.y;
        sX[r*65 + c4*4+2] = v.z; sX[r*65 + c4*4+3] = v.w;
    }
    __syncthreads();

    int rp = tid >> 3, cg = tid & 7;
    int r0 = rp * 4;
    int cA = cg * 4, cB = 32 + cg * 4;
    float4 attA = __ldg((const float4*)&att[cA]);
    float4 attB = __ldg((const float4*)&att[cB]);

    unsigned long long acc2[4][4];
#pragma unroll
    for (int i = 0; i < 4; i++)
#pragma unroll
        for (int p = 0; p < 4; p++) acc2[i][p] = 0ULL;

#pragma unroll 8
    for (int k = 0; k < 64; k++){
        // two adjacent fp32 in smem ARE a packed f32x2: load pairs directly
        ulonglong2 wA = *(const ulonglong2*)&sW[k*64 + cA];
        ulonglong2 wB = *(const ulonglong2*)&sW[k*64 + cB];
#pragma unroll
        for (int i = 0; i < 4; i++){
            float xv = sX[(r0 + i)*65 + k];
            unsigned long long xv2 = pk2(xv, xv);
            fma2(acc2[i][0], xv2, wA.x);
            fma2(acc2[i][1], xv2, wA.y);
            fma2(acc2[i][2], xv2, wB.x);
            fma2(acc2[i][3], xv2, wB.y);
        }
    }

#pragma unroll
    for (int i = 0; i < 4; i++){
        float a0,a1,a2,a3,a4,a5,a6,a7;
        upk2(acc2[i][0], a0, a1);
        upk2(acc2[i][1], a2, a3);
        upk2(acc2[i][2], a4, a5);
        upk2(acc2[i][3], a6, a7);
        int gr = row0 + r0 + i;
        float pA = a0*attA.x + a1*attA.y + a2*attA.z + a3*attA.w;
        float pB = a4*attB.x + a5*attB.y + a6*attB.z + a7*attB.w;
        pA += __shfl_xor_sync(0xffffffffu, pA, 1);
        pA += __shfl_xor_sync(0xffffffffu, pA, 2);
        pB += __shfl_xor_sync(0xffffffffu, pB, 1);
        pB += __shfl_xor_sync(0xffffffffu, pB, 2);
        if (gr < N){
            union { __half2 h2[2]; uint2 u; } pk;
            pk.h2[0] = __floats2half2_rn(a0, a1);
            pk.h2[1] = __floats2half2_rn(a2, a3);
            *(uint2*)&hs[(size_t)gr*64 + cA] = pk.u;
            pk.h2[0] = __floats2half2_rn(a4, a5);
            pk.h2[1] = __floats2half2_rn(a6, a7);
            *(uint2*)&hs[(size_t)gr*64 + cB] = pk.u;
            if ((cg & 3) == 0){
                int h01 = cg >> 2;
                as[gr*4 + h01]     = pA;
                as[gr*4 + 2 + h01] = pB;
            }
        }
    }
}

// ---------------------------------------------------------------------------
// merged a_d: user dst (t1,t2,t3,t7) blocks [0,3125), article (t0,t5) after.
// ---------------------------------------------------------------------------
__global__ void k_ad_all(const float* __restrict__ Wdst,
                         const float* __restrict__ attd, int l){
    __shared__ float sWd[4][64][4];
    __shared__ float sX[64][65];
    int b = blockIdx.x;
    int dst_sel, N, nT, row0;
    int tl[4], dofs[4];
    if (b < 3125){
        dst_sel = 0; N = NU; nT = 4; row0 = b * 64;
        tl[0]=1; tl[1]=2; tl[2]=3; tl[3]=7;
        dofs[0]=100000; dofs[1]=300000; dofs[2]=500000; dofs[3]=800000;
    } else {
        dst_sel = 1; N = NA; nT = 2; row0 = (b - 3125) * 64;
        tl[0]=0; tl[1]=5; tl[2]=0; tl[3]=0;
        dofs[0]=0; dofs[1]=700000; dofs[2]=0; dofs[3]=0;
    }
    const float* x = xp(dst_sel);
    int tid = threadIdx.x;

    {
        int k = tid >> 2, h = tid & 3;
#pragma unroll
        for (int q = 0; q < 4; q++){
            if (q < nT){
                const float* Wd = Wdst + (size_t)(l*8 + tl[q]) * 4096;
                const float* at = attd + (size_t)(l*8 + tl[q]) * 64;
                float s = 0.f;
#pragma unroll
                for (int c = 0; c < 16; c++) s += Wd[k*64 + h*16 + c] * at[h*16 + c];
                sWd[q][k][h] = s;
            }
        }
    }
    for (int i = tid; i < 4096; i += 256){
        int r = i >> 6, c = i & 63;
        int gr = row0 + r;
        sX[r][c] = (gr < N) ? x[gr*64 + c] : 0.f;
    }
    __syncthreads();

    int r = tid >> 2, h = tid & 3;
    int gr = row0 + r;
    if (gr < N){
#pragma unroll
        for (int q = 0; q < 4; q++){
            if (q < nT){
                float s = 0.f;
#pragma unroll
                for (int k = 0; k < 64; k++) s += sX[r][k] * sWd[q][k][h];
                g_adA[(size_t)(dofs[q] + gr)*4 + h] = s;
            }
        }
    }
}

// ---------------------------------------------------------------------------
// merged cat a_d: t4 and t6 folded vectors; also zero partial buffers.
// ---------------------------------------------------------------------------
__global__ void k_ad_cat(const float* __restrict__ Wdst,
                         const float* __restrict__ attd, int l){
    __shared__ float sWd[2][64][4];
    __shared__ float sX[64][65];
    int tid = threadIdx.x;
    const int tl[2] = {4, 6};
    {
        int k = tid >> 2, h = tid & 3;
#pragma unroll
        for (int q = 0; q < 2; q++){
            const float* Wd = Wdst + (size_t)(l*8 + tl[q]) * 4096;
            const float* at = attd + (size_t)(l*8 + tl[q]) * 64;
            float s = 0.f;
#pragma unroll
            for (int c = 0; c < 16; c++) s += Wd[k*64 + h*16 + c] * at[h*16 + c];
            sWd[q][k][h] = s;
        }
    }
    int row0 = blockIdx.x * 64;
    for (int i = tid; i < 4096; i += 256){
        int r = i >> 6, c = i & 63;
        int gr = row0 + r;
        sX[r][c] = (gr < NC) ? g_xc[gr*64 + c] : 0.f;
    }
    __syncthreads();

    int r = tid >> 2, h = tid & 3;
    int gr = row0 + r;
    if (gr < NC){
        float s4 = 0.f, s6 = 0.f;
#pragma unroll
        for (int k = 0; k < 64; k++){
            float xv = sX[r][k];
            s4 += xv * sWd[0][k][h];
            s6 += xv * sWd[1][k][h];
        }
        g_adc4[gr*4 + h] = s4;
        g_adc6[gr*4 + h] = s6;
        g_denc0[gr*4 + h] = 0.f;
        g_denc1[gr*4 + h] = 0.f;
        float4 z = make_float4(0.f,0.f,0.f,0.f);
        float4* t0 = (float4*)&g_tmpc0[gr*64 + h*16];
        float4* t1 = (float4*)&g_tmpc1[gr*64 + h*16];
        t0[0]=z; t0[1]=z; t0[2]=z; t0[3]=z;
        t1[0]=z; t1[1]=z; t1[2]=z; t1[3]=z;
    }
}

// ---------------------------------------------------------------------------
// edge segment body, half2 layout (R12-proven)
// ---------------------------------------------------------------------------
__device__ __forceinline__ void do_edges(const int* __restrict__ rows, int beg, int end,
                                         const __half* __restrict__ hs,
                                         const float* __restrict__ as,
                                         int lane, int h, float adh,
                                         float& a0, float& a1, float& d){
    const __half2* hs2 = (const __half2*)hs;
    int e = beg;
    for (; e + 4 <= end; e += 4){
        int r0 = __ldg(rows + e + 0), r1 = __ldg(rows + e + 1);
        int r2 = __ldg(rows + e + 2), r3 = __ldg(rows + e + 3);
        float s0 = __ldg(&as[r0*4 + h]);
        float s1 = __ldg(&as[r1*4 + h]);
        float s2 = __ldg(&as[r2*4 + h]);
        float s3 = __ldg(&as[r3*4 + h]);
        __half2 u0 = __ldg(&hs2[(size_t)r0*32 + lane]);
        __half2 u1 = __ldg(&hs2[(size_t)r1*32 + lane]);
        __half2 u2 = __ldg(&hs2[(size_t)r2*32 + lane]);
        __half2 u3 = __ldg(&hs2[(size_t)r3*32 + lane]);

        float e0 = s0 + adh, e1 = s1 + adh, e2 = s2 + adh, e3 = s3 + adh;
        e0 = e0 > 0.f ? e0 : 0.2f*e0;
        e1 = e1 > 0.f ? e1 : 0.2f*e1;
        e2 = e2 > 0.f ? e2 : 0.2f*e2;
        e3 = e3 > 0.f ? e3 : 0.2f*e3;
        float x0 = __expf(e0), x1 = __expf(e1), x2 = __expf(e2), x3 = __expf(e3);

        float2 f0 = __half22float2(u0);
        float2 f1 = __half22float2(u1);
        float2 f2 = __half22float2(u2);
        float2 f3 = __half22float2(u3);
        a0 += x0*f0.x + x1*f1.x + x2*f2.x + x3*f3.x;
        a1 += x0*f0.y + x1*f1.y + x2*f2.y + x3*f3.y;
        d  += x0 + x1 + x2 + x3;
    }
    for (; e < end; e++){
        int row = __ldg(rows + e);
        float ev = __ldg(&as[row*4 + h]) + adh;
        ev = ev > 0.f ? ev : 0.2f*ev;
        float ex = __expf(ev);
        float2 f = __half22float2(__ldg(&hs2[(size_t)row*32 + lane]));
        a0 += ex*f.x; a1 += ex*f.y; d += ex;
    }
}

__device__ __forceinline__ void aggr_one(int t, int gw, int eoff, int hsoff, int adoff,
                                         int lane, int h, float& o0, float& o1){
    int beg = g_indptr[t][gw], end = g_indptr[t][gw + 1];
    if (beg >= end) return;
    float adh = g_adA[(size_t)(adoff + gw)*4 + h];
    float a0 = 0.f, a1 = 0.f, d = 0.f;
    do_edges(g_rows + eoff, beg, end,
             g_hsA + (size_t)hsoff*64, g_asA + (size_t)hsoff*4,
             lane, h, adh, a0, a1, d);
    float inv = 1.f / (d + 1e-16f);
    o0 += a0 * inv;
    o1 += a1 * inv;
}

// ---------------------------------------------------------------------------
// merged aggregation: warps [0,NU) user nodes, [NU,NU+NA) article nodes.
// ---------------------------------------------------------------------------
__global__ void k_aggr_all(int e0, int e1, int e2, int e3, int e5, int e7,
                           const float* __restrict__ bias, int l){
    int gwid = (blockIdx.x * blockDim.x + threadIdx.x) >> 5;
    int lane = threadIdx.x & 31, h = lane >> 3;
    int c0 = 2*lane, c1 = 2*lane + 1;
    const float* bl = bias + l*512;

    if (gwid < NU){
        int gw = gwid;
        float o0 = bl[64+c0] + bl[128+c0] + bl[192+c0] + bl[448+c0];
        float o1 = bl[64+c1] + bl[128+c1] + bl[192+c1] + bl[448+c1];
        aggr_one(1, gw, e1, 200000,  100000, lane, h, o0, o1);
        aggr_one(2, gw, e2, 300000,  300000, lane, h, o0, o1);
        aggr_one(3, gw, e3, 500000,  500000, lane, h, o0, o1);
        aggr_one(7, gw, e7, 1000500, 800000, lane, h, o0, o1);
        float v0 = o0 > 0.f ? o0 : 0.01f*o0;
        float v1 = o1 > 0.f ? o1 : 0.01f*o1;
        *(float2*)&g_xu[(size_t)gw*64 + c0] = make_float2(v0, v1);
        float2 au = *(float2*)&g_accu[(size_t)gw*64 + c0];
        au.x += v0; au.y += v1;
        *(float2*)&g_accu[(size_t)gw*64 + c0] = au;
    } else if (gwid < NU + NA){
        int gw = gwid - NU;
        float o0 = bl[0+c0] + bl[320+c0];
        float o1 = bl[0+c1] + bl[320+c1];
        aggr_one(0, gw, e0, 0,      0,      lane, h, o0, o1);
        aggr_one(5, gw, e5, 800000, 700000, lane, h, o0, o1);
        float v0 = o0 > 0.f ? o0 : 0.01f*o0;
        float v1 = o1 > 0.f ? o1 : 0.01f*o1;
        *(float2*)&g_xa[(size_t)gw*64 + c0] = make_float2(v0, v1);
        float2 au = *(float2*)&g_acci[(size_t)gw*64 + c0];
        au.x += v0; au.y += v1;
        *(float2*)&g_acci[(size_t)gw*64 + c0] = au;
    }
}

// ---------------------------------------------------------------------------
// merged category aggregation
// ---------------------------------------------------------------------------
#define CCHUNK 64
__device__ __forceinline__ void cat_chunks(int t, int eoff, int E, int hsoff,
                                           const float* __restrict__ adc,
                                           float* __restrict__ tmpc,
                                           float* __restrict__ denc,
                                           int w, int lane){
    int es = w * CCHUNK;
    if (es >= E) return;
    int ee = min(es + CCHUNK, E);
    const int* __restrict__ ip = g_indptr[t];
    int lo = 0, hi = NC;
    while (lo < hi){
        int mid = (lo + hi + 1) >> 1;
        if (ip[mid] <= es) lo = mid; else hi = mid - 1;
    }
    int n = lo;
    int h = lane >> 3;
    int c0 = 2*lane;
    const int* rows = g_rows + eoff;
    const __half* hs = g_hsA + (size_t)hsoff*64;
    const float* as = g_asA + (size_t)hsoff*4;

    while (es < ee){
        int segend = min(ip[n + 1], ee);
        float adh = adc[n*4 + h];
        float a0 = 0.f, a1 = 0.f, d = 0.f;
        do_edges(rows, es, segend, hs, as, lane, h, adh, a0, a1, d);
        atomicAdd(&tmpc[n*64 + c0],     a0);
        atomicAdd(&tmpc[n*64 + c0 + 1], a1);
        if ((lane & 7) == 0)
            atomicAdd(&denc[n*4 + h], d);
        es = segend;
        n++;
    }
}

__global__ void k_aggr_cat_all(int eoff4, int E4, int eoff6, int E6){
    int w = (blockIdx.x * blockDim.x + threadIdx.x) >> 5;
    int lane = threadIdx.x & 31;
    int ch4 = (E4 + CCHUNK - 1) / CCHUNK;
    if (w < ch4){
        cat_chunks(4, eoff4, E4, 700000, g_adc4, g_tmpc0, g_denc0, w, lane);
    } else {
        cat_chunks(6, eoff6, E6, 800500, g_adc6, g_tmpc1, g_denc1, w - ch4, lane);
    }
}

__global__ void k_cat_final(const float* __restrict__ bias, int l){
    int i = blockIdx.x * blockDim.x + threadIdx.x;
    if (i >= NC*DD) return;
    int n = i >> 6, c = i & 63, h = c >> 4;
    const float* bl = bias + l*512;
    float v = g_tmpc0[i] / (g_denc0[n*4 + h] + 1e-16f)
            + g_tmpc1[i] / (g_denc1[n*4 + h] + 1e-16f)
            + bl[256 + c] + bl[384 + c];
    g_xc[i] = v > 0.f ? v : 0.01f*v;
}

// ---------------------------------------------------------------------------
__global__ void k_final(float* __restrict__ out){
    int i = blockIdx.x * blockDim.x + threadIdx.x;
    const int nu = NU * DD;
    const int tot = nu + NA * DD;
    if (i >= tot) return;
    const float s = 1.f / 3.f;
    out[i] = (i < nu) ? g_accu[i] * s : g_acci[i - nu] * s;
}

// ---------------------------------------------------------------------------
static inline int cdiv(long long a, int b){ return (int)((a + b - 1) / b); }

extern "C" void kernel_launch(void* const* d_in, const int* in_sizes, int n_in,
                              void* d_out, int out_size){
    const float* x_user    = (const float*)d_in[0];
    const float* x_article = (const float*)d_in[1];
    const float* x_cat     = (const float*)d_in[2];
    const float* Wsrc      = (const float*)d_in[3];
    const float* Wdst      = (const float*)d_in[4];
    const float* att_src   = (const float*)d_in[5];
    const float* att_dst   = (const float*)d_in[6];
    const float* bias      = (const float*)d_in[7];
    float* out = (float*)d_out;

    cudaFuncSetAttribute(k_gemm_all, cudaFuncAttributeMaxDynamicSharedMemorySize, GEMM_SMEM);

    int EN[8], CUM[9]; CUM[0] = 0;
    for (int t = 0; t < 8; t++){ EN[t] = in_sizes[8 + t] / 2; CUM[t+1] = CUM[t] + EN[t]; }
    const int* EP[8];
    for (int t = 0; t < 8; t++) EP[t] = (const int*)d_in[8 + t];

    const int TOTN = (NU + NA + NC) * DD;

    k_init     <<<cdiv(TOTN, 256), 256>>>(x_user, x_article, x_cat);
    k_count_all<<<cdiv(CUM[8], 256), 256>>>(EP[0],EP[1],EP[2],EP[3],EP[4],EP[5],EP[6],EP[7],
                                            CUM[1],CUM[2],CUM[3],CUM[4],CUM[5],CUM[6],CUM[7],CUM[8]);
    k_scan1    <<<NBLK_SCAN, 1024>>>();
    // #4 PROFILED: batched layer-0 GEMM
    k_gemm_all <<<GEMM_BLOCKS, 256, GEMM_SMEM>>>(Wsrc, att_src, 0);
    k_scan2    <<<1, 256>>>();
    k_scan3    <<<cdiv(8*(NU+1), 256), 256>>>(EN[0],EN[1],EN[2],EN[3],EN[4],EN[5],EN[6],EN[7]);
    k_fill_all <<<cdiv(CUM[8], 256), 256>>>(EP[0],EP[1],EP[2],EP[3],EP[4],EP[5],EP[6],EP[7],
                                            CUM[1],CUM[2],CUM[3],CUM[4],CUM[5],CUM[6],CUM[7],CUM[8]);

    for (int l = 0; l < 2; l++){
        if (l > 0)
            k_gemm_all<<<GEMM_BLOCKS, 256, GEMM_SMEM>>>(Wsrc, att_src, l);
        k_ad_all <<<3125 + 1563, 256>>>(Wdst, att_dst, l);
        k_ad_cat <<<cdiv(NC, 64), 256>>>(Wdst, att_dst, l);
        k_aggr_all<<<cdiv(NU + NA, 8), 256>>>(CUM[0], CUM[1], CUM[2], CUM[3],
                                              CUM[5], CUM[7], bias, l);
        {
            int ch = cdiv(EN[4], CCHUNK) + cdiv(EN[6], CCHUNK);
            k_aggr_cat_all<<<cdiv(ch, 8), 256>>>(CUM[4], EN[4], CUM[6], EN[6]);
        }
        k_cat_final<<<cdiv(NC*DD, 256), 256>>>(bias, l);
    }

    k_final<<<cdiv((long long)(NU + NA) * DD, 256), 256>>>(out);
}